// round 13
// baseline (speedup 1.0000x reference)
#include <cuda_runtime.h>
#include <cuda_bf16.h>
#include <math.h>
#include <stdint.h>

typedef __nv_bfloat16 bf16;

#define BB 2
#define NN 2048
#define HH 16
#define MTOT (BB*NN)          // 4096
#define BHT (BB*HH)           // 32

// ======================= scratch (no cudaMalloc allowed) =======================
__device__ __align__(256) bf16  g_xh[(size_t)MTOT * 1024];
__device__ __align__(256) bf16  g_xl[(size_t)MTOT * 1024];
__device__ __align__(256) bf16  g_wqTh[(size_t)3072 * 1024];
__device__ __align__(256) bf16  g_wqTl[(size_t)3072 * 1024];
__device__ __align__(256) bf16  g_woTh[(size_t)1024 * 1024];
__device__ __align__(256) bf16  g_woTl[(size_t)1024 * 1024];
__device__ __align__(256) bf16  g_Qh[(size_t)BHT * NN * 64];
__device__ __align__(256) bf16  g_Ql[(size_t)BHT * NN * 64];
__device__ __align__(256) bf16  g_Kh[(size_t)BHT * NN * 64];
__device__ __align__(256) bf16  g_Kl[(size_t)BHT * NN * 64];
__device__ __align__(256) bf16  g_Vth[(size_t)BHT * 64 * NN];   // [bh, d, n]
__device__ __align__(256) bf16  g_Vtl[(size_t)BHT * 64 * NN];
__device__ __align__(256) bf16  g_aOh[(size_t)MTOT * 1024];
__device__ __align__(256) bf16  g_aOl[(size_t)MTOT * 1024];
__device__ __align__(256) float g_cs[(size_t)NN * 32 * 2];      // rope cos/sin table

// ======================= helpers =======================
__device__ __forceinline__ uint32_t smem_to_u32(const void* p) {
    uint32_t a;
    asm("{ .reg .u64 t; cvta.to.shared.u64 t, %1; cvt.u32.u64 %0, t; }" : "=r"(a) : "l"(p));
    return a;
}
__device__ __forceinline__ void cp16(uint32_t s, const void* g) {
    asm volatile("cp.async.cg.shared.global [%0], [%1], 16;" :: "r"(s), "l"(g) : "memory");
}
__device__ __forceinline__ void ldm_x4(uint32_t* r, uint32_t addr) {
    asm volatile("ldmatrix.sync.aligned.m8n8.x4.shared.b16 {%0,%1,%2,%3}, [%4];"
                 : "=r"(r[0]), "=r"(r[1]), "=r"(r[2]), "=r"(r[3]) : "r"(addr));
}
__device__ __forceinline__ void mma16816(float* d, const uint32_t* a,
                                         uint32_t b0, uint32_t b1) {
    asm volatile(
        "mma.sync.aligned.m16n8k16.row.col.f32.bf16.bf16.f32 "
        "{%0,%1,%2,%3}, {%4,%5,%6,%7}, {%8,%9}, {%0,%1,%2,%3};"
        : "+f"(d[0]), "+f"(d[1]), "+f"(d[2]), "+f"(d[3])
        : "r"(a[0]), "r"(a[1]), "r"(a[2]), "r"(a[3]), "r"(b0), "r"(b1));
}
__device__ __forceinline__ float ex2(float x) {
    float y;
    asm("ex2.approx.f32 %0, %1;" : "=f"(y) : "f"(x));
    return y;
}
__device__ __forceinline__ void split2(float v, bf16* H, bf16* L, size_t o) {
    bf16 hb = __float2bfloat16(v);
    H[o] = hb;
    L[o] = __float2bfloat16(v - __bfloat162float(hb));
}
// swizzle for 64B-wide rows (GEMM tiles)
__device__ __forceinline__ uint32_t sw64(int row, int c16) {
    return (uint32_t)(row * 64 + ((c16 ^ ((row >> 1) & 3)) << 4));
}
// standard 128B swizzle for 128B-wide rows (flash tiles)
__device__ __forceinline__ uint32_t sw128(uint32_t off) {
    return off ^ ((off >> 3) & 0x70);
}

// ======================= HMMA bf16-split GEMM =======================
// C = (Ah+Al)[M,K] @ (Bh+Bl)[N,K]^T.  128x128 CTA tile, BK=32, 3-stage.
// 4 warps (2x2), warp tile 64x64: 16 LDSM -> 96 MMA per ks (flash-like fatness).
// EPI=0: write fp32 C.  EPI=1: fused rope/split/transpose epilogue for qkv.
template <int EPI>
__global__ __launch_bounds__(128, 2)
void mma_gemm_kernel(const bf16* __restrict__ Ah, const bf16* __restrict__ Al,
                     const bf16* __restrict__ Bh, const bf16* __restrict__ Bl,
                     float* __restrict__ C, int K, int ldC,
                     const float* __restrict__ cs,
                     bf16* __restrict__ Qh, bf16* __restrict__ Ql,
                     bf16* __restrict__ Kh, bf16* __restrict__ Kl,
                     bf16* __restrict__ Vth, bf16* __restrict__ Vtl) {
    constexpr int ABYTES = 128 * 64;   // 8192
    constexpr int BBYTES = 128 * 64;
    constexpr int STAGE  = 2 * ABYTES + 2 * BBYTES;   // 32768

    extern __shared__ char smem[];
    uint32_t sb = smem_to_u32(smem);

    int tid = threadIdx.x;
    int lane = tid & 31, wid = tid >> 5;
    int wm = wid & 1, wn = wid >> 1;      // 2x2 warp grid, 64x64 tiles

    int n0 = blockIdx.x * 128;
    int m0 = blockIdx.y * 128;

    float acc[4][8][4];
#pragma unroll
    for (int i = 0; i < 4; i++)
#pragma unroll
        for (int j = 0; j < 8; j++)
#pragma unroll
            for (int c = 0; c < 4; c++) acc[i][j][c] = 0.f;

    const int nkt = K >> 5;

    auto load_tiles = [&](int kt, int buf) {
        uint32_t base = sb + buf * STAGE;
#pragma unroll
        for (int it = 0; it < 4; it++) {
            int i = tid + it * 128;
            int r = i >> 2, c = i & 3;
            size_t g = (size_t)(m0 + r) * K + (size_t)kt * 32 + c * 8;
            uint32_t so = base + sw64(r, c);
            cp16(so, Ah + g);
            cp16(so + ABYTES, Al + g);
        }
#pragma unroll
        for (int it = 0; it < 4; it++) {
            int i = tid + it * 128;
            int r = i >> 2, c = i & 3;
            size_t g = (size_t)(n0 + r) * K + (size_t)kt * 32 + c * 8;
            uint32_t so = base + 2 * ABYTES + sw64(r, c);
            cp16(so, Bh + g);
            cp16(so + BBYTES, Bl + g);
        }
    };

    load_tiles(0, 0);
    asm volatile("cp.async.commit_group;" ::: "memory");
    if (nkt > 1) {
        load_tiles(1, 1);
        asm volatile("cp.async.commit_group;" ::: "memory");
    }

    int stage = 0;
    for (int kt = 0; kt < nkt; kt++) {
        if (kt < nkt - 1) {
            asm volatile("cp.async.wait_group 1;" ::: "memory");
        } else {
            asm volatile("cp.async.wait_group 0;" ::: "memory");
        }
        __syncthreads();

        if (kt + 2 < nkt) {
            int nb = stage + 2; if (nb >= 3) nb -= 3;
            load_tiles(kt + 2, nb);
            asm volatile("cp.async.commit_group;" ::: "memory");
        }

        uint32_t abase = sb + stage * STAGE;
        uint32_t bbase = abase + 2 * ABYTES;

#pragma unroll
        for (int ks = 0; ks < 2; ks++) {
            int arow = wm * 64 + (lane & 15);
            int brow = wn * 64 + (lane & 15);
            int c16  = ks * 2 + (lane >> 4);

            uint32_t ah[4][4], al[4][4];
#pragma unroll
            for (int i = 0; i < 4; i++) {
                uint32_t ad = abase + sw64(arow + i * 16, c16);
                ldm_x4(ah[i], ad);
                ldm_x4(al[i], ad + ABYTES);
            }
            uint32_t bh[4][4], bl[4][4];
#pragma unroll
            for (int g = 0; g < 4; g++) {
                uint32_t bd = bbase + sw64(brow + g * 16, c16);
                ldm_x4(bh[g], bd);
                ldm_x4(bl[g], bd + BBYTES);
            }

            // 96 MMAs per ks, product-major (32 independent per pass)
#pragma unroll
            for (int i = 0; i < 4; i++)
#pragma unroll
                for (int j = 0; j < 8; j++) {
                    int g = j >> 1, hf = j & 1;
                    mma16816(acc[i][j], ah[i], bh[g][hf], bh[g][hf + 2]);
                }
#pragma unroll
            for (int i = 0; i < 4; i++)
#pragma unroll
                for (int j = 0; j < 8; j++) {
                    int g = j >> 1, hf = j & 1;
                    mma16816(acc[i][j], ah[i], bl[g][hf], bl[g][hf + 2]);
                }
#pragma unroll
            for (int i = 0; i < 4; i++)
#pragma unroll
                for (int j = 0; j < 8; j++) {
                    int g = j >> 1, hf = j & 1;
                    mma16816(acc[i][j], al[i], bh[g][hf], bh[g][hf + 2]);
                }
        }
        if (++stage == 3) stage = 0;
    }

    int r0 = lane >> 2, c0 = (lane & 3) * 2;

    if (EPI == 0) {
#pragma unroll
        for (int i = 0; i < 4; i++) {
            int row = m0 + wm * 64 + i * 16 + r0;
#pragma unroll
            for (int j = 0; j < 8; j++) {
                int col = n0 + wn * 64 + j * 8 + c0;
                *(float2*)&C[(size_t)row * ldC + col] =
                    make_float2(acc[i][j][0], acc[i][j][1]);
                *(float2*)&C[(size_t)(row + 8) * ldC + col] =
                    make_float2(acc[i][j][2], acc[i][j][3]);
            }
        }
        return;
    }

    // ===== fused qkv epilogue: stage acc tile through smem (128 x 129 f32) =====
    __syncthreads();
    float* st = (float*)smem;
#pragma unroll
    for (int i = 0; i < 4; i++) {
        int row = wm * 64 + i * 16 + r0;
#pragma unroll
        for (int j = 0; j < 8; j++) {
            int col = wn * 64 + j * 8 + c0;
            st[row * 129 + col]           = acc[i][j][0];
            st[row * 129 + col + 1]       = acc[i][j][1];
            st[(row + 8) * 129 + col]     = acc[i][j][2];
            st[(row + 8) * 129 + col + 1] = acc[i][j][3];
        }
    }
    __syncthreads();

    int mt = n0 >> 10;                // 0=q, 1=k, 2=v
    int h0 = (n0 & 1023) >> 6;        // first head in this tile (even)
    int nbase = m0 & 2047;
    int bb = m0 >> 11;

    if (mt < 2) {
        // RoPE + split into Q or K, [bh, n, 64]; 128 threads cover 2 heads x 128 rows
        int i  = tid & 31;
        int hh = (tid >> 5) & 1;
        int rg = tid >> 6;            // 0..1, 64 rows each
        bf16* Hh = (mt == 0) ? Qh : Kh;
        bf16* Hl = (mt == 0) ? Ql : Kl;
        const float sc = (mt == 0) ? 0.125f * 1.44269504089f : 1.0f;
        size_t bhb = ((size_t)(bb * HH + h0 + hh)) * NN;
        int hcol = hh * 64;
#pragma unroll 4
        for (int rr = 0; rr < 64; rr++) {
            int r = rg * 64 + rr;
            int n = nbase + r;
            float v1 = st[r * 129 + hcol + i];
            float v2 = st[r * 129 + hcol + i + 32];
            float2 csv = *(const float2*)&cs[(n * 32 + i) * 2];
            float a1 = sc * (v1 * csv.x - v2 * csv.y);
            float a2 = sc * (v2 * csv.x + v1 * csv.y);
            size_t ob = (bhb + n) * 64;
            split2(a1, Hh, Hl, ob + i);
            split2(a2, Hh, Hl, ob + i + 32);
        }
    } else {
        // V transpose + split into Vt [bh, d, n]
        int hh = tid >> 6;            // 0..1
        int np = (tid & 63) * 2;      // row pair
        size_t vb = ((size_t)(bb * HH + h0 + hh)) * 64;
        int hcol = hh * 64;
#pragma unroll 4
        for (int d = 0; d < 64; d++) {
            float v0 = st[np * 129 + hcol + d];
            float v1 = st[(np + 1) * 129 + hcol + d];
            __nv_bfloat162 hv = __floats2bfloat162_rn(v0, v1);
            __nv_bfloat162 lv = __floats2bfloat162_rn(v0 - __bfloat162float(hv.x),
                                                      v1 - __bfloat162float(hv.y));
            size_t off = (vb + d) * NN + nbase + np;
            *(__nv_bfloat162*)&Vth[off] = hv;
            *(__nv_bfloat162*)&Vtl[off] = lv;
        }
    }
}

// ======================= fused flash attention (HMMA, bf16-split) ==============
// Per CTA: 64 q rows of one (b,h), 4 warps x 16 rows, 128 threads, 128B swizzle.
__global__ __launch_bounds__(128, 3)
void flash_kernel(const bf16* __restrict__ Qh_, const bf16* __restrict__ Ql_,
                  const bf16* __restrict__ Kh_, const bf16* __restrict__ Kl_,
                  const bf16* __restrict__ Vh_, const bf16* __restrict__ Vl_,
                  bf16* __restrict__ aOh, bf16* __restrict__ aOl) {
    constexpr int FTILE = 8192;       // 64 rows x 128B, swizzled
    constexpr int FSTG  = 4 * FTILE;  // Kh,Kl,Vh,Vl

    extern __shared__ char smem[];
    uint32_t sb = smem_to_u32(smem);
    int tid = threadIdx.x, lane = tid & 31, wid = tid >> 5;
    int q0 = blockIdx.x * 64;
    int bh = blockIdx.y;
    int b = bh >> 4, h = bh & 15;

    const bf16* Qhp = Qh_ + ((size_t)bh * NN + q0) * 64;
    const bf16* Qlp = Ql_ + ((size_t)bh * NN + q0) * 64;
    const bf16* Khp = Kh_ + (size_t)bh * NN * 64;
    const bf16* Klp = Kl_ + (size_t)bh * NN * 64;
    const bf16* Vhp = Vh_ + (size_t)bh * 64 * NN;
    const bf16* Vlp = Vl_ + (size_t)bh * 64 * NN;

#pragma unroll
    for (int it = 0; it < 4; it++) {
        int i = tid + it * 128;
        int r = i >> 3, c = i & 7;
        uint32_t so = sw128((uint32_t)(r * 128 + c * 16));
        cp16(sb + so, Qhp + r * 64 + c * 8);
        cp16(sb + FTILE + so, Qlp + r * 64 + c * 8);
    }
    asm volatile("cp.async.commit_group;" ::: "memory");

    auto load_kv = [&](int kt, int buf) {
        uint32_t base = sb + buf * FSTG;
        int kv0 = kt * 64;
#pragma unroll
        for (int it = 0; it < 16; it++) {
            int i = tid + it * 128;
            int mat = i >> 9;
            int slot = i & 511;
            int r = slot >> 3, c = slot & 7;
            uint32_t so = base + mat * FTILE + sw128((uint32_t)(r * 128 + c * 16));
            const bf16* g;
            if (mat == 0)      g = Khp + (size_t)(kv0 + r) * 64 + c * 8;
            else if (mat == 1) g = Klp + (size_t)(kv0 + r) * 64 + c * 8;
            else if (mat == 2) g = Vhp + (size_t)r * NN + kv0 + c * 8;
            else               g = Vlp + (size_t)r * NN + kv0 + c * 8;
            cp16(so, g);
        }
    };

    load_kv(0, 1);
    asm volatile("cp.async.commit_group;" ::: "memory");
    asm volatile("cp.async.wait_group 1;" ::: "memory");
    __syncthreads();

    uint32_t qh[4][4], ql[4][4];
    {
        int arow = wid * 16 + (lane & 15);
#pragma unroll
        for (int ks = 0; ks < 4; ks++) {
            int c16 = ks * 2 + (lane >> 4);
            uint32_t so = sw128((uint32_t)(arow * 128 + c16 * 16));
            ldm_x4(qh[ks], sb + so);
            ldm_x4(ql[ks], sb + FTILE + so);
        }
    }
    __syncthreads();

    float o[8][4];
#pragma unroll
    for (int j = 0; j < 8; j++)
#pragma unroll
        for (int c = 0; c < 4; c++) o[j][c] = 0.f;
    float lpart[2] = {0.f, 0.f};

    for (int kt = 0; kt < NN / 64; kt++) {
        int cur = (kt + 1) & 1;
        if (kt + 1 < NN / 64) {
            load_kv(kt + 1, kt & 1);
            asm volatile("cp.async.commit_group;" ::: "memory");
            asm volatile("cp.async.wait_group 1;" ::: "memory");
        } else {
            asm volatile("cp.async.wait_group 0;" ::: "memory");
        }
        __syncthreads();

        uint32_t kb = sb + cur * FSTG;
        uint32_t vb = kb + 2 * FTILE;

        float s[8][4];
#pragma unroll
        for (int j = 0; j < 8; j++)
#pragma unroll
            for (int c = 0; c < 4; c++) s[j][c] = 0.f;
        {
            int brow = lane & 15;
#pragma unroll
            for (int ks = 0; ks < 4; ks++) {
                int c16 = ks * 2 + (lane >> 4);
                uint32_t khf[4][4], klf[4][4];
#pragma unroll
                for (int g = 0; g < 4; g++) {
                    uint32_t so = sw128((uint32_t)((g * 16 + brow) * 128 + c16 * 16));
                    ldm_x4(khf[g], kb + so);
                    ldm_x4(klf[g], kb + FTILE + so);
                }
#pragma unroll
                for (int g = 0; g < 4; g++)
#pragma unroll
                    for (int hf = 0; hf < 2; hf++)
                        mma16816(s[g * 2 + hf], qh[ks], khf[g][hf], khf[g][hf + 2]);
#pragma unroll
                for (int g = 0; g < 4; g++)
#pragma unroll
                    for (int hf = 0; hf < 2; hf++)
                        mma16816(s[g * 2 + hf], qh[ks], klf[g][hf], klf[g][hf + 2]);
#pragma unroll
                for (int g = 0; g < 4; g++)
#pragma unroll
                    for (int hf = 0; hf < 2; hf++)
                        mma16816(s[g * 2 + hf], ql[ks], khf[g][hf], khf[g][hf + 2]);
            }
        }

        {
            int vrow = lane & 15;
#pragma unroll
            for (int kc = 0; kc < 4; kc++) {
                uint32_t pa[4], pl[4];
#pragma unroll
                for (int t = 0; t < 2; t++) {
                    int j = kc * 2 + t;
#pragma unroll
                    for (int e = 0; e < 4; e++) s[j][e] = ex2(s[j][e]);
                    lpart[0] += s[j][0] + s[j][1];
                    lpart[1] += s[j][2] + s[j][3];
#pragma unroll
                    for (int e = 0; e < 2; e++) {
                        float x = s[j][e * 2], y = s[j][e * 2 + 1];
                        __nv_bfloat162 hv = __floats2bfloat162_rn(x, y);
                        float lx = x - __bfloat162float(hv.x);
                        float ly = y - __bfloat162float(hv.y);
                        __nv_bfloat162 lv = __floats2bfloat162_rn(lx, ly);
                        pa[t * 2 + e] = *(uint32_t*)&hv;
                        pl[t * 2 + e] = *(uint32_t*)&lv;
                    }
                }
                uint32_t vhf[4][4], vlf[4][4];
#pragma unroll
                for (int g = 0; g < 4; g++) {
                    int c16 = kc * 2 + (lane >> 4);
                    uint32_t so = sw128((uint32_t)((g * 16 + vrow) * 128 + c16 * 16));
                    ldm_x4(vhf[g], vb + so);
                    ldm_x4(vlf[g], vb + FTILE + so);
                }
#pragma unroll
                for (int g = 0; g < 4; g++)
#pragma unroll
                    for (int hf = 0; hf < 2; hf++)
                        mma16816(o[g * 2 + hf], pa, vhf[g][hf], vhf[g][hf + 2]);
#pragma unroll
                for (int g = 0; g < 4; g++)
#pragma unroll
                    for (int hf = 0; hf < 2; hf++)
                        mma16816(o[g * 2 + hf], pl, vhf[g][hf], vhf[g][hf + 2]);
#pragma unroll
                for (int g = 0; g < 4; g++)
#pragma unroll
                    for (int hf = 0; hf < 2; hf++)
                        mma16816(o[g * 2 + hf], pa, vlf[g][hf], vlf[g][hf + 2]);
            }
        }
        __syncthreads();
    }

    float lrow[2];
#pragma unroll
    for (int half = 0; half < 2; half++) {
        float rs = lpart[half];
        rs += __shfl_xor_sync(0xffffffffu, rs, 1);
        rs += __shfl_xor_sync(0xffffffffu, rs, 2);
        lrow[half] = rs;
    }
    float inv0 = 1.f / lrow[0], inv1 = 1.f / lrow[1];
    int r0 = q0 + wid * 16 + (lane >> 2);
    int cb = (lane & 3) * 2;
    size_t row0 = ((size_t)b * NN + r0) * 1024 + h * 64;
    size_t row1 = row0 + (size_t)8 * 1024;
#pragma unroll
    for (int dj = 0; dj < 8; dj++) {
        int col = dj * 8 + cb;
        float v0 = o[dj][0] * inv0, v1 = o[dj][1] * inv0;
        __nv_bfloat162 hv = __floats2bfloat162_rn(v0, v1);
        __nv_bfloat162 lv = __floats2bfloat162_rn(v0 - __bfloat162float(hv.x),
                                                  v1 - __bfloat162float(hv.y));
        *(__nv_bfloat162*)&aOh[row0 + col] = hv;
        *(__nv_bfloat162*)&aOl[row0 + col] = lv;
        float v2 = o[dj][2] * inv1, v3 = o[dj][3] * inv1;
        hv = __floats2bfloat162_rn(v2, v3);
        lv = __floats2bfloat162_rn(v2 - __bfloat162float(hv.x),
                                   v3 - __bfloat162float(hv.y));
        *(__nv_bfloat162*)&aOh[row1 + col] = hv;
        *(__nv_bfloat162*)&aOl[row1 + col] = lv;
    }
}

// ======================= merged preprocessing (one launch) =======================
// blocks [0,3072): wqkv transpose; [3072,4096): wout transpose;
// [4096,8192): split x; [8192,8448): rope table.
__device__ __forceinline__ void wtrans_body(const float* __restrict__ W,
                                            bf16* __restrict__ Th, bf16* __restrict__ Tl,
                                            int K, int N, int n0, int k0, int tid,
                                            float (*t)[33]) {
    int tx = tid & 31, ty = tid >> 5;
#pragma unroll
    for (int s = 0; s < 32; s += 8)
        t[ty + s][tx] = W[(size_t)(k0 + ty + s) * N + n0 + tx];
    __syncthreads();
#pragma unroll
    for (int s = 0; s < 32; s += 8) {
        float v = t[tx][ty + s];
        split2(v, Th, Tl, (size_t)(n0 + ty + s) * K + k0 + tx);
    }
}

__global__ __launch_bounds__(256)
void prep_kernel(const float* __restrict__ x, const float* __restrict__ w_qkv,
                 const float* __restrict__ w_out,
                 bf16* __restrict__ xh, bf16* __restrict__ xl,
                 bf16* __restrict__ wqTh, bf16* __restrict__ wqTl,
                 bf16* __restrict__ woTh, bf16* __restrict__ woTl,
                 float* __restrict__ cs) {
    __shared__ float t[32][33];
    int bid = blockIdx.x;
    int tid = threadIdx.x;
    if (bid < 3072) {
        wtrans_body(w_qkv, wqTh, wqTl, 1024, 3072,
                    (bid % 96) * 32, (bid / 96) * 32, tid, t);
    } else if (bid < 4096) {
        int id = bid - 3072;
        wtrans_body(w_out, woTh, woTl, 1024, 1024,
                    (id & 31) * 32, (id >> 5) * 32, tid, t);
    } else if (bid < 8192) {
        int i = ((bid - 4096) * 256 + tid) * 4;
        float4 v = *(const float4*)(x + i);
        __nv_bfloat162 h0 = __floats2bfloat162_rn(v.x, v.y);
        __nv_bfloat162 h1 = __floats2bfloat162_rn(v.z, v.w);
        __nv_bfloat162 l0 = __floats2bfloat162_rn(v.x - __bfloat162float(h0.x),
                                                  v.y - __bfloat162float(h0.y));
        __nv_bfloat162 l1 = __floats2bfloat162_rn(v.z - __bfloat162float(h1.x),
                                                  v.w - __bfloat162float(h1.y));
        *(__nv_bfloat162*)&xh[i]     = h0;
        *(__nv_bfloat162*)&xh[i + 2] = h1;
        *(__nv_bfloat162*)&xl[i]     = l0;
        *(__nv_bfloat162*)&xl[i + 2] = l1;
    } else {
        int idx = (bid - 8192) * 256 + tid;
        int n = idx >> 5, i = idx & 31;
        double inv = pow(10000.0, -(double)i / 32.0);
        double ang = (double)n * inv;
        cs[idx * 2]     = (float)cos(ang);
        cs[idx * 2 + 1] = (float)sin(ang);
    }
}

// ======================= launch =======================
extern "C" void kernel_launch(void* const* d_in, const int* in_sizes, int n_in,
                              void* d_out, int out_size) {
    const float* x     = (const float*)d_in[0];
    const float* w_qkv = (const float*)d_in[1];
    const float* w_out = (const float*)d_in[2];
    float* out = (float*)d_out;

    float *cs;
    bf16 *xh, *xl, *wqTh, *wqTl, *woTh, *woTl;
    bf16 *Qh, *Ql, *Kh, *Kl, *Vth, *Vtl, *aOh, *aOl;
    cudaGetSymbolAddress((void**)&cs,  g_cs);
    cudaGetSymbolAddress((void**)&xh,  g_xh);   cudaGetSymbolAddress((void**)&xl,  g_xl);
    cudaGetSymbolAddress((void**)&wqTh, g_wqTh); cudaGetSymbolAddress((void**)&wqTl, g_wqTl);
    cudaGetSymbolAddress((void**)&woTh, g_woTh); cudaGetSymbolAddress((void**)&woTl, g_woTl);
    cudaGetSymbolAddress((void**)&Qh, g_Qh);    cudaGetSymbolAddress((void**)&Ql, g_Ql);
    cudaGetSymbolAddress((void**)&Kh, g_Kh);    cudaGetSymbolAddress((void**)&Kl, g_Kl);
    cudaGetSymbolAddress((void**)&Vth, g_Vth);  cudaGetSymbolAddress((void**)&Vtl, g_Vtl);
    cudaGetSymbolAddress((void**)&aOh, g_aOh);  cudaGetSymbolAddress((void**)&aOl, g_aOl);

    const int SMEM_GEMM = 3 * 32768;       // 98304 (>= 128*129*4 for epilogue)
    const int FLASH_SMEM = 2 * 4 * 8192;   // 65536
    cudaFuncSetAttribute(mma_gemm_kernel<0>,
                         cudaFuncAttributeMaxDynamicSharedMemorySize, SMEM_GEMM);
    cudaFuncSetAttribute(mma_gemm_kernel<1>,
                         cudaFuncAttributeMaxDynamicSharedMemorySize, SMEM_GEMM);
    cudaFuncSetAttribute(flash_kernel,
                         cudaFuncAttributeMaxDynamicSharedMemorySize, FLASH_SMEM);

    // 0) merged preprocessing: weight transposes + x split + rope table
    prep_kernel<<<8448, 256>>>(x, w_qkv, w_out, xh, xl, wqTh, wqTl, woTh, woTl, cs);

    // 1) qkv GEMM with fused rope/split/transpose epilogue
    mma_gemm_kernel<1><<<dim3(3072 / 128, 4096 / 128), 128, SMEM_GEMM>>>(
        xh, xl, wqTh, wqTl, nullptr, 1024, 0,
        cs, Qh, Ql, Kh, Kl, Vth, Vtl);

    // 2) fused flash attention -> aOh/aOl [B*N, 1024]
    flash_kernel<<<dim3(NN / 64, BHT), 128, FLASH_SMEM>>>(
        Qh, Ql, Kh, Kl, Vth, Vtl, aOh, aOl);

    // 3) out = aO @ w_out  (M=4096, N=1024, K=1024)
    mma_gemm_kernel<0><<<dim3(1024 / 128, 4096 / 128), 128, SMEM_GEMM>>>(
        aOh, aOl, woTh, woTl, out, 1024, 1024,
        nullptr, nullptr, nullptr, nullptr, nullptr, nullptr, nullptr);
}

// round 14
// speedup vs baseline: 1.0025x; 1.0025x over previous
#include <cuda_runtime.h>
#include <cuda_bf16.h>
#include <math.h>
#include <stdint.h>

typedef __nv_bfloat16 bf16;

#define BB 2
#define NN 2048
#define HH 16
#define MTOT (BB*NN)          // 4096
#define BHT (BB*HH)           // 32

// ======================= scratch (no cudaMalloc allowed) =======================
__device__ __align__(256) bf16  g_xh[(size_t)MTOT * 1024];
__device__ __align__(256) bf16  g_xl[(size_t)MTOT * 1024];
__device__ __align__(256) bf16  g_wqTh[(size_t)3072 * 1024];
__device__ __align__(256) bf16  g_wqTl[(size_t)3072 * 1024];
__device__ __align__(256) bf16  g_woTh[(size_t)1024 * 1024];
__device__ __align__(256) bf16  g_woTl[(size_t)1024 * 1024];
__device__ __align__(256) bf16  g_Qh[(size_t)BHT * NN * 64];
__device__ __align__(256) bf16  g_Ql[(size_t)BHT * NN * 64];
__device__ __align__(256) bf16  g_Kh[(size_t)BHT * NN * 64];
__device__ __align__(256) bf16  g_Kl[(size_t)BHT * NN * 64];
__device__ __align__(256) bf16  g_Vth[(size_t)BHT * 64 * NN];   // [bh, d, n]
__device__ __align__(256) bf16  g_Vtl[(size_t)BHT * 64 * NN];
__device__ __align__(256) bf16  g_aOh[(size_t)MTOT * 1024];
__device__ __align__(256) bf16  g_aOl[(size_t)MTOT * 1024];
__device__ __align__(256) float g_cs[(size_t)NN * 32 * 2];      // rope cos/sin table

// ======================= helpers =======================
__device__ __forceinline__ uint32_t smem_to_u32(const void* p) {
    uint32_t a;
    asm("{ .reg .u64 t; cvta.to.shared.u64 t, %1; cvt.u32.u64 %0, t; }" : "=r"(a) : "l"(p));
    return a;
}
__device__ __forceinline__ void cp16(uint32_t s, const void* g) {
    asm volatile("cp.async.cg.shared.global [%0], [%1], 16;" :: "r"(s), "l"(g) : "memory");
}
__device__ __forceinline__ void ldm_x4(uint32_t* r, uint32_t addr) {
    asm volatile("ldmatrix.sync.aligned.m8n8.x4.shared.b16 {%0,%1,%2,%3}, [%4];"
                 : "=r"(r[0]), "=r"(r[1]), "=r"(r[2]), "=r"(r[3]) : "r"(addr));
}
__device__ __forceinline__ void mma16816(float* d, const uint32_t* a,
                                         uint32_t b0, uint32_t b1) {
    asm volatile(
        "mma.sync.aligned.m16n8k16.row.col.f32.bf16.bf16.f32 "
        "{%0,%1,%2,%3}, {%4,%5,%6,%7}, {%8,%9}, {%0,%1,%2,%3};"
        : "+f"(d[0]), "+f"(d[1]), "+f"(d[2]), "+f"(d[3])
        : "r"(a[0]), "r"(a[1]), "r"(a[2]), "r"(a[3]), "r"(b0), "r"(b1));
}
__device__ __forceinline__ float ex2(float x) {
    float y;
    asm("ex2.approx.f32 %0, %1;" : "=f"(y) : "f"(x));
    return y;
}
__device__ __forceinline__ void split2(float v, bf16* H, bf16* L, size_t o) {
    bf16 hb = __float2bfloat16(v);
    H[o] = hb;
    L[o] = __float2bfloat16(v - __bfloat162float(hb));
}
// swizzle for 64B-wide rows (GEMM tiles)
__device__ __forceinline__ uint32_t sw64(int row, int c16) {
    return (uint32_t)(row * 64 + ((c16 ^ ((row >> 1) & 3)) << 4));
}
// standard 128B swizzle for 128B-wide rows (flash tiles)
__device__ __forceinline__ uint32_t sw128(uint32_t off) {
    return off ^ ((off >> 3) & 0x70);
}

// ======================= HMMA bf16-split GEMM (R11 config) =======================
// C = (Ah+Al)[M,K] @ (Bh+Bl)[N,K]^T.  128x128 tile, BK=32, 256 thr (8 warps 2x4),
// warp tile 64x32, 3-stage cp.async, 64B swizzle.
// EPI=0: write fp32 C.  EPI=1: fused rope/split/transpose epilogue for qkv.
template <int EPI>
__global__ __launch_bounds__(256)
void mma_gemm_kernel(const bf16* __restrict__ Ah, const bf16* __restrict__ Al,
                     const bf16* __restrict__ Bh, const bf16* __restrict__ Bl,
                     float* __restrict__ C, int K, int ldC,
                     const float* __restrict__ cs,
                     bf16* __restrict__ Qh, bf16* __restrict__ Ql,
                     bf16* __restrict__ Kh, bf16* __restrict__ Kl,
                     bf16* __restrict__ Vth, bf16* __restrict__ Vtl) {
    constexpr int ABYTES = 128 * 64;   // 8192
    constexpr int BBYTES = 128 * 64;
    constexpr int STAGE  = 2 * ABYTES + 2 * BBYTES;   // 32768

    extern __shared__ char smem[];
    uint32_t sb = smem_to_u32(smem);

    int tid = threadIdx.x;
    int lane = tid & 31, wid = tid >> 5;
    int wm = wid & 1, wn = wid >> 1;      // 2x4 warp grid, warp tile 64x32

    int n0 = blockIdx.x * 128;
    int m0 = blockIdx.y * 128;

    float acc[4][4][4];
#pragma unroll
    for (int i = 0; i < 4; i++)
#pragma unroll
        for (int j = 0; j < 4; j++)
#pragma unroll
            for (int c = 0; c < 4; c++) acc[i][j][c] = 0.f;

    const int nkt = K >> 5;

    auto load_tiles = [&](int kt, int buf) {
        uint32_t base = sb + buf * STAGE;
#pragma unroll
        for (int it = 0; it < 2; it++) {
            int i = tid + it * 256;
            int r = i >> 2, c = i & 3;
            size_t g = (size_t)(m0 + r) * K + (size_t)kt * 32 + c * 8;
            uint32_t so = base + sw64(r, c);
            cp16(so, Ah + g);
            cp16(so + ABYTES, Al + g);
        }
#pragma unroll
        for (int it = 0; it < 2; it++) {
            int i = tid + it * 256;
            int r = i >> 2, c = i & 3;
            size_t g = (size_t)(n0 + r) * K + (size_t)kt * 32 + c * 8;
            uint32_t so = base + 2 * ABYTES + sw64(r, c);
            cp16(so, Bh + g);
            cp16(so + BBYTES, Bl + g);
        }
    };

    load_tiles(0, 0);
    asm volatile("cp.async.commit_group;" ::: "memory");
    if (nkt > 1) {
        load_tiles(1, 1);
        asm volatile("cp.async.commit_group;" ::: "memory");
    }

    int stage = 0;
    for (int kt = 0; kt < nkt; kt++) {
        if (kt < nkt - 1) {
            asm volatile("cp.async.wait_group 1;" ::: "memory");
        } else {
            asm volatile("cp.async.wait_group 0;" ::: "memory");
        }
        __syncthreads();

        if (kt + 2 < nkt) {
            int nb = stage + 2; if (nb >= 3) nb -= 3;
            load_tiles(kt + 2, nb);
            asm volatile("cp.async.commit_group;" ::: "memory");
        }

        uint32_t abase = sb + stage * STAGE;
        uint32_t bbase = abase + 2 * ABYTES;

#pragma unroll
        for (int ks = 0; ks < 2; ks++) {
            int arow = wm * 64 + (lane & 15);
            int c16  = ks * 2 + (lane >> 4);

            uint32_t ah[4][4], al[4][4];
#pragma unroll
            for (int i = 0; i < 4; i++) {
                uint32_t ad = abase + sw64(arow + i * 16, c16);
                ldm_x4(ah[i], ad);
                ldm_x4(al[i], ad + ABYTES);
            }

            uint32_t bh[2][4], bl[2][4];
            int brow = wn * 32 + (lane & 15);
#pragma unroll
            for (int g = 0; g < 2; g++) {
                uint32_t bd = bbase + sw64(brow + g * 16, c16);
                ldm_x4(bh[g], bd);
                ldm_x4(bl[g], bd + BBYTES);
            }

#pragma unroll
            for (int i = 0; i < 4; i++)
#pragma unroll
                for (int j = 0; j < 4; j++) {
                    int g = j >> 1, hf = j & 1;
                    uint32_t b0h = bh[g][hf], b1h = bh[g][hf + 2];
                    uint32_t b0l = bl[g][hf], b1l = bl[g][hf + 2];
                    mma16816(acc[i][j], ah[i], b0h, b1h);
                    mma16816(acc[i][j], ah[i], b0l, b1l);
                    mma16816(acc[i][j], al[i], b0h, b1h);
                }
        }
        if (++stage == 3) stage = 0;
    }

    int r0 = lane >> 2, c0 = (lane & 3) * 2;

    if (EPI == 0) {
#pragma unroll
        for (int i = 0; i < 4; i++) {
            int row = m0 + wm * 64 + i * 16 + r0;
#pragma unroll
            for (int j = 0; j < 4; j++) {
                int col = n0 + wn * 32 + j * 8 + c0;
                *(float2*)&C[(size_t)row * ldC + col] =
                    make_float2(acc[i][j][0], acc[i][j][1]);
                *(float2*)&C[(size_t)(row + 8) * ldC + col] =
                    make_float2(acc[i][j][2], acc[i][j][3]);
            }
        }
        return;
    }

    // ===== fused qkv epilogue: stage acc tile through smem (128 x 129 f32) =====
    __syncthreads();
    float* st = (float*)smem;
#pragma unroll
    for (int i = 0; i < 4; i++) {
        int row = wm * 64 + i * 16 + r0;
#pragma unroll
        for (int j = 0; j < 4; j++) {
            int col = wn * 32 + j * 8 + c0;
            st[row * 129 + col]           = acc[i][j][0];
            st[row * 129 + col + 1]       = acc[i][j][1];
            st[(row + 8) * 129 + col]     = acc[i][j][2];
            st[(row + 8) * 129 + col + 1] = acc[i][j][3];
        }
    }
    __syncthreads();

    int mt = n0 >> 10;                // 0=q, 1=k, 2=v
    int h0 = (n0 & 1023) >> 6;        // first head in this tile (even)
    int nbase = m0 & 2047;
    int bb = m0 >> 11;

    if (mt < 2) {
        // RoPE + split into Q or K, [bh, n, 64]
        int i  = tid & 31;
        int hh = (tid >> 5) & 1;
        int rg = tid >> 6;            // 4 row groups of 32
        bf16* Hh = (mt == 0) ? Qh : Kh;
        bf16* Hl = (mt == 0) ? Ql : Kl;
        const float sc = (mt == 0) ? 0.125f * 1.44269504089f : 1.0f;
        size_t bhb = ((size_t)(bb * HH + h0 + hh)) * NN;
        int hcol = hh * 64;
#pragma unroll 4
        for (int rr = 0; rr < 32; rr++) {
            int r = rg * 32 + rr;
            int n = nbase + r;
            float v1 = st[r * 129 + hcol + i];
            float v2 = st[r * 129 + hcol + i + 32];
            float2 csv = *(const float2*)&cs[(n * 32 + i) * 2];
            float a1 = sc * (v1 * csv.x - v2 * csv.y);
            float a2 = sc * (v2 * csv.x + v1 * csv.y);
            size_t ob = (bhb + n) * 64;
            split2(a1, Hh, Hl, ob + i);
            split2(a2, Hh, Hl, ob + i + 32);
        }
    } else {
        // V transpose + split into Vt [bh, d, n]
        int hh = tid >> 7;            // 0..1
        int dh = (tid >> 6) & 1;      // d half
        int np = (tid & 63) * 2;      // row pair
        size_t vb = ((size_t)(bb * HH + h0 + hh)) * 64;
        int hcol = hh * 64;
#pragma unroll 4
        for (int dd = 0; dd < 32; dd++) {
            int d = dh * 32 + dd;
            float v0 = st[np * 129 + hcol + d];
            float v1 = st[(np + 1) * 129 + hcol + d];
            __nv_bfloat162 hv = __floats2bfloat162_rn(v0, v1);
            __nv_bfloat162 lv = __floats2bfloat162_rn(v0 - __bfloat162float(hv.x),
                                                      v1 - __bfloat162float(hv.y));
            size_t off = (vb + d) * NN + nbase + np;
            *(__nv_bfloat162*)&Vth[off] = hv;
            *(__nv_bfloat162*)&Vtl[off] = lv;
        }
    }
}

// ======================= fused flash attention (HMMA, bf16-split) ==============
// Per CTA: 64 q rows of one (b,h), 4 warps x 16 rows, 128 threads, 128B swizzle.
// V-fragment LDSMs hoisted above exp/pack so smem latency overlaps MUFU/ALU chains.
__global__ __launch_bounds__(128, 3)
void flash_kernel(const bf16* __restrict__ Qh_, const bf16* __restrict__ Ql_,
                  const bf16* __restrict__ Kh_, const bf16* __restrict__ Kl_,
                  const bf16* __restrict__ Vh_, const bf16* __restrict__ Vl_,
                  bf16* __restrict__ aOh, bf16* __restrict__ aOl) {
    constexpr int FTILE = 8192;       // 64 rows x 128B, swizzled
    constexpr int FSTG  = 4 * FTILE;  // Kh,Kl,Vh,Vl

    extern __shared__ char smem[];
    uint32_t sb = smem_to_u32(smem);
    int tid = threadIdx.x, lane = tid & 31, wid = tid >> 5;
    int q0 = blockIdx.x * 64;
    int bh = blockIdx.y;
    int b = bh >> 4, h = bh & 15;

    const bf16* Qhp = Qh_ + ((size_t)bh * NN + q0) * 64;
    const bf16* Qlp = Ql_ + ((size_t)bh * NN + q0) * 64;
    const bf16* Khp = Kh_ + (size_t)bh * NN * 64;
    const bf16* Klp = Kl_ + (size_t)bh * NN * 64;
    const bf16* Vhp = Vh_ + (size_t)bh * 64 * NN;
    const bf16* Vlp = Vl_ + (size_t)bh * 64 * NN;

#pragma unroll
    for (int it = 0; it < 4; it++) {
        int i = tid + it * 128;
        int r = i >> 3, c = i & 7;
        uint32_t so = sw128((uint32_t)(r * 128 + c * 16));
        cp16(sb + so, Qhp + r * 64 + c * 8);
        cp16(sb + FTILE + so, Qlp + r * 64 + c * 8);
    }
    asm volatile("cp.async.commit_group;" ::: "memory");

    auto load_kv = [&](int kt, int buf) {
        uint32_t base = sb + buf * FSTG;
        int kv0 = kt * 64;
#pragma unroll
        for (int it = 0; it < 16; it++) {
            int i = tid + it * 128;
            int mat = i >> 9;
            int slot = i & 511;
            int r = slot >> 3, c = slot & 7;
            uint32_t so = base + mat * FTILE + sw128((uint32_t)(r * 128 + c * 16));
            const bf16* g;
            if (mat == 0)      g = Khp + (size_t)(kv0 + r) * 64 + c * 8;
            else if (mat == 1) g = Klp + (size_t)(kv0 + r) * 64 + c * 8;
            else if (mat == 2) g = Vhp + (size_t)r * NN + kv0 + c * 8;
            else               g = Vlp + (size_t)r * NN + kv0 + c * 8;
            cp16(so, g);
        }
    };

    load_kv(0, 1);
    asm volatile("cp.async.commit_group;" ::: "memory");
    asm volatile("cp.async.wait_group 1;" ::: "memory");
    __syncthreads();

    uint32_t qh[4][4], ql[4][4];
    {
        int arow = wid * 16 + (lane & 15);
#pragma unroll
        for (int ks = 0; ks < 4; ks++) {
            int c16 = ks * 2 + (lane >> 4);
            uint32_t so = sw128((uint32_t)(arow * 128 + c16 * 16));
            ldm_x4(qh[ks], sb + so);
            ldm_x4(ql[ks], sb + FTILE + so);
        }
    }
    __syncthreads();

    float o[8][4];
#pragma unroll
    for (int j = 0; j < 8; j++)
#pragma unroll
        for (int c = 0; c < 4; c++) o[j][c] = 0.f;
    float lpart[2] = {0.f, 0.f};

    for (int kt = 0; kt < NN / 64; kt++) {
        int cur = (kt + 1) & 1;
        if (kt + 1 < NN / 64) {
            load_kv(kt + 1, kt & 1);
            asm volatile("cp.async.commit_group;" ::: "memory");
            asm volatile("cp.async.wait_group 1;" ::: "memory");
        } else {
            asm volatile("cp.async.wait_group 0;" ::: "memory");
        }
        __syncthreads();

        uint32_t kb = sb + cur * FSTG;
        uint32_t vb = kb + 2 * FTILE;

        // ---- S = Q @ K^T (0.125*log2e pre-folded into Q) ----
        float s[8][4];
#pragma unroll
        for (int j = 0; j < 8; j++)
#pragma unroll
            for (int c = 0; c < 4; c++) s[j][c] = 0.f;
        {
            int brow = lane & 15;
#pragma unroll
            for (int ks = 0; ks < 4; ks++) {
                int c16 = ks * 2 + (lane >> 4);
                uint32_t khf[4][4], klf[4][4];
#pragma unroll
                for (int g = 0; g < 4; g++) {
                    uint32_t so = sw128((uint32_t)((g * 16 + brow) * 128 + c16 * 16));
                    ldm_x4(khf[g], kb + so);
                    ldm_x4(klf[g], kb + FTILE + so);
                }
#pragma unroll
                for (int g = 0; g < 4; g++)
#pragma unroll
                    for (int hf = 0; hf < 2; hf++) {
                        int j = g * 2 + hf;
                        mma16816(s[j], qh[ks], khf[g][hf], khf[g][hf + 2]);
                        mma16816(s[j], qh[ks], klf[g][hf], klf[g][hf + 2]);
                        mma16816(s[j], ql[ks], khf[g][hf], khf[g][hf + 2]);
                    }
            }
        }

        // ---- per-kc: V LDSM first (latency overlaps exp/pack), then PV ----
        {
            int vrow = lane & 15;
#pragma unroll
            for (int kc = 0; kc < 4; kc++) {
                uint32_t vhf[4][4], vlf[4][4];
#pragma unroll
                for (int g = 0; g < 4; g++) {
                    int c16 = kc * 2 + (lane >> 4);
                    uint32_t so = sw128((uint32_t)((g * 16 + vrow) * 128 + c16 * 16));
                    ldm_x4(vhf[g], vb + so);
                    ldm_x4(vlf[g], vb + FTILE + so);
                }

                uint32_t pa[4], pl[4];
#pragma unroll
                for (int t = 0; t < 2; t++) {
                    int j = kc * 2 + t;
#pragma unroll
                    for (int e = 0; e < 4; e++) s[j][e] = ex2(s[j][e]);
                    lpart[0] += s[j][0] + s[j][1];
                    lpart[1] += s[j][2] + s[j][3];
#pragma unroll
                    for (int e = 0; e < 2; e++) {
                        float x = s[j][e * 2], y = s[j][e * 2 + 1];
                        __nv_bfloat162 hv = __floats2bfloat162_rn(x, y);
                        float lx = x - __bfloat162float(hv.x);
                        float ly = y - __bfloat162float(hv.y);
                        __nv_bfloat162 lv = __floats2bfloat162_rn(lx, ly);
                        pa[t * 2 + e] = *(uint32_t*)&hv;
                        pl[t * 2 + e] = *(uint32_t*)&lv;
                    }
                }

#pragma unroll
                for (int g = 0; g < 4; g++)
#pragma unroll
                    for (int hf = 0; hf < 2; hf++) {
                        int dj = g * 2 + hf;
                        mma16816(o[dj], pa, vhf[g][hf], vhf[g][hf + 2]);
                        mma16816(o[dj], pl, vhf[g][hf], vhf[g][hf + 2]);
                        mma16816(o[dj], pa, vlf[g][hf], vlf[g][hf + 2]);
                    }
            }
        }
        __syncthreads();
    }

    // ---- epilogue: reduce row sums, normalize, split, write ----
    float lrow[2];
#pragma unroll
    for (int half = 0; half < 2; half++) {
        float rs = lpart[half];
        rs += __shfl_xor_sync(0xffffffffu, rs, 1);
        rs += __shfl_xor_sync(0xffffffffu, rs, 2);
        lrow[half] = rs;
    }
    float inv0 = 1.f / lrow[0], inv1 = 1.f / lrow[1];
    int r0 = q0 + wid * 16 + (lane >> 2);
    int cb = (lane & 3) * 2;
    size_t row0 = ((size_t)b * NN + r0) * 1024 + h * 64;
    size_t row1 = row0 + (size_t)8 * 1024;
#pragma unroll
    for (int dj = 0; dj < 8; dj++) {
        int col = dj * 8 + cb;
        float v0 = o[dj][0] * inv0, v1 = o[dj][1] * inv0;
        __nv_bfloat162 hv = __floats2bfloat162_rn(v0, v1);
        __nv_bfloat162 lv = __floats2bfloat162_rn(v0 - __bfloat162float(hv.x),
                                                  v1 - __bfloat162float(hv.y));
        *(__nv_bfloat162*)&aOh[row0 + col] = hv;
        *(__nv_bfloat162*)&aOl[row0 + col] = lv;
        float v2 = o[dj][2] * inv1, v3 = o[dj][3] * inv1;
        hv = __floats2bfloat162_rn(v2, v3);
        lv = __floats2bfloat162_rn(v2 - __bfloat162float(hv.x),
                                   v3 - __bfloat162float(hv.y));
        *(__nv_bfloat162*)&aOh[row1 + col] = hv;
        *(__nv_bfloat162*)&aOl[row1 + col] = lv;
    }
}

// ======================= merged preprocessing (one launch) =======================
__device__ __forceinline__ void wtrans_body(const float* __restrict__ W,
                                            bf16* __restrict__ Th, bf16* __restrict__ Tl,
                                            int K, int N, int n0, int k0, int tid,
                                            float (*t)[33]) {
    int tx = tid & 31, ty = tid >> 5;
#pragma unroll
    for (int s = 0; s < 32; s += 8)
        t[ty + s][tx] = W[(size_t)(k0 + ty + s) * N + n0 + tx];
    __syncthreads();
#pragma unroll
    for (int s = 0; s < 32; s += 8) {
        float v = t[tx][ty + s];
        split2(v, Th, Tl, (size_t)(n0 + ty + s) * K + k0 + tx);
    }
}

__global__ __launch_bounds__(256)
void prep_kernel(const float* __restrict__ x, const float* __restrict__ w_qkv,
                 const float* __restrict__ w_out,
                 bf16* __restrict__ xh, bf16* __restrict__ xl,
                 bf16* __restrict__ wqTh, bf16* __restrict__ wqTl,
                 bf16* __restrict__ woTh, bf16* __restrict__ woTl,
                 float* __restrict__ cs) {
    __shared__ float t[32][33];
    int bid = blockIdx.x;
    int tid = threadIdx.x;
    if (bid < 3072) {
        wtrans_body(w_qkv, wqTh, wqTl, 1024, 3072,
                    (bid % 96) * 32, (bid / 96) * 32, tid, t);
    } else if (bid < 4096) {
        int id = bid - 3072;
        wtrans_body(w_out, woTh, woTl, 1024, 1024,
                    (id & 31) * 32, (id >> 5) * 32, tid, t);
    } else if (bid < 8192) {
        int i = ((bid - 4096) * 256 + tid) * 4;
        float4 v = *(const float4*)(x + i);
        __nv_bfloat162 h0 = __floats2bfloat162_rn(v.x, v.y);
        __nv_bfloat162 h1 = __floats2bfloat162_rn(v.z, v.w);
        __nv_bfloat162 l0 = __floats2bfloat162_rn(v.x - __bfloat162float(h0.x),
                                                  v.y - __bfloat162float(h0.y));
        __nv_bfloat162 l1 = __floats2bfloat162_rn(v.z - __bfloat162float(h1.x),
                                                  v.w - __bfloat162float(h1.y));
        *(__nv_bfloat162*)&xh[i]     = h0;
        *(__nv_bfloat162*)&xh[i + 2] = h1;
        *(__nv_bfloat162*)&xl[i]     = l0;
        *(__nv_bfloat162*)&xl[i + 2] = l1;
    } else {
        int idx = (bid - 8192) * 256 + tid;
        int n = idx >> 5, i = idx & 31;
        double inv = pow(10000.0, -(double)i / 32.0);
        double ang = (double)n * inv;
        cs[idx * 2]     = (float)cos(ang);
        cs[idx * 2 + 1] = (float)sin(ang);
    }
}

// ======================= launch =======================
extern "C" void kernel_launch(void* const* d_in, const int* in_sizes, int n_in,
                              void* d_out, int out_size) {
    const float* x     = (const float*)d_in[0];
    const float* w_qkv = (const float*)d_in[1];
    const float* w_out = (const float*)d_in[2];
    float* out = (float*)d_out;

    float *cs;
    bf16 *xh, *xl, *wqTh, *wqTl, *woTh, *woTl;
    bf16 *Qh, *Ql, *Kh, *Kl, *Vth, *Vtl, *aOh, *aOl;
    cudaGetSymbolAddress((void**)&cs,  g_cs);
    cudaGetSymbolAddress((void**)&xh,  g_xh);   cudaGetSymbolAddress((void**)&xl,  g_xl);
    cudaGetSymbolAddress((void**)&wqTh, g_wqTh); cudaGetSymbolAddress((void**)&wqTl, g_wqTl);
    cudaGetSymbolAddress((void**)&woTh, g_woTh); cudaGetSymbolAddress((void**)&woTl, g_woTl);
    cudaGetSymbolAddress((void**)&Qh, g_Qh);    cudaGetSymbolAddress((void**)&Ql, g_Ql);
    cudaGetSymbolAddress((void**)&Kh, g_Kh);    cudaGetSymbolAddress((void**)&Kl, g_Kl);
    cudaGetSymbolAddress((void**)&Vth, g_Vth);  cudaGetSymbolAddress((void**)&Vtl, g_Vtl);
    cudaGetSymbolAddress((void**)&aOh, g_aOh);  cudaGetSymbolAddress((void**)&aOl, g_aOl);

    const int SMEM_GEMM = 3 * 32768;       // 98304 (>= 128*129*4 for epilogue)
    const int FLASH_SMEM = 2 * 4 * 8192;   // 65536
    cudaFuncSetAttribute(mma_gemm_kernel<0>,
                         cudaFuncAttributeMaxDynamicSharedMemorySize, SMEM_GEMM);
    cudaFuncSetAttribute(mma_gemm_kernel<1>,
                         cudaFuncAttributeMaxDynamicSharedMemorySize, SMEM_GEMM);
    cudaFuncSetAttribute(flash_kernel,
                         cudaFuncAttributeMaxDynamicSharedMemorySize, FLASH_SMEM);

    // 0) merged preprocessing: weight transposes + x split + rope table
    prep_kernel<<<8448, 256>>>(x, w_qkv, w_out, xh, xl, wqTh, wqTl, woTh, woTl, cs);

    // 1) qkv GEMM with fused rope/split/transpose epilogue
    mma_gemm_kernel<1><<<dim3(3072 / 128, 4096 / 128), 256, SMEM_GEMM>>>(
        xh, xl, wqTh, wqTl, nullptr, 1024, 0,
        cs, Qh, Ql, Kh, Kl, Vth, Vtl);

    // 2) fused flash attention -> aOh/aOl [B*N, 1024]
    flash_kernel<<<dim3(NN / 64, BHT), 128, FLASH_SMEM>>>(
        Qh, Ql, Kh, Kl, Vth, Vtl, aOh, aOl);

    // 3) out = aO @ w_out  (M=4096, N=1024, K=1024)
    mma_gemm_kernel<0><<<dim3(1024 / 128, 4096 / 128), 256, SMEM_GEMM>>>(
        aOh, aOl, woTh, woTl, out, 1024, 1024,
        nullptr, nullptr, nullptr, nullptr, nullptr, nullptr, nullptr);
}

// round 15
// speedup vs baseline: 1.0566x; 1.0540x over previous
#include <cuda_runtime.h>
#include <cuda_bf16.h>
#include <math.h>
#include <stdint.h>

typedef __nv_bfloat16 bf16;

#define BB 2
#define NN 2048
#define HH 16
#define MTOT (BB*NN)          // 4096
#define BHT (BB*HH)           // 32

// ======================= scratch (no cudaMalloc allowed) =======================
__device__ __align__(256) bf16  g_xh[(size_t)MTOT * 1024];
__device__ __align__(256) bf16  g_xl[(size_t)MTOT * 1024];
__device__ __align__(256) bf16  g_wqTh[(size_t)3072 * 1024];
__device__ __align__(256) bf16  g_wqTl[(size_t)3072 * 1024];
__device__ __align__(256) bf16  g_woTh[(size_t)1024 * 1024];
__device__ __align__(256) bf16  g_woTl[(size_t)1024 * 1024];
__device__ __align__(256) bf16  g_Qh[(size_t)BHT * NN * 64];
__device__ __align__(256) bf16  g_Ql[(size_t)BHT * NN * 64];
__device__ __align__(256) bf16  g_Kh[(size_t)BHT * NN * 64];
__device__ __align__(256) bf16  g_Kl[(size_t)BHT * NN * 64];
__device__ __align__(256) bf16  g_Vth[(size_t)BHT * 64 * NN];   // [bh, d, n]
__device__ __align__(256) bf16  g_Vtl[(size_t)BHT * 64 * NN];
__device__ __align__(256) bf16  g_aOh[(size_t)MTOT * 1024];
__device__ __align__(256) bf16  g_aOl[(size_t)MTOT * 1024];
__device__ __align__(256) float g_cs[(size_t)NN * 32 * 2];      // rope cos/sin table

// ======================= helpers =======================
__device__ __forceinline__ uint32_t smem_to_u32(const void* p) {
    uint32_t a;
    asm("{ .reg .u64 t; cvta.to.shared.u64 t, %1; cvt.u32.u64 %0, t; }" : "=r"(a) : "l"(p));
    return a;
}
__device__ __forceinline__ void cp16(uint32_t s, const void* g) {
    asm volatile("cp.async.cg.shared.global [%0], [%1], 16;" :: "r"(s), "l"(g) : "memory");
}
__device__ __forceinline__ void ldm_x4(uint32_t* r, uint32_t addr) {
    asm volatile("ldmatrix.sync.aligned.m8n8.x4.shared.b16 {%0,%1,%2,%3}, [%4];"
                 : "=r"(r[0]), "=r"(r[1]), "=r"(r[2]), "=r"(r[3]) : "r"(addr));
}
__device__ __forceinline__ void mma16816(float* d, const uint32_t* a,
                                         uint32_t b0, uint32_t b1) {
    asm volatile(
        "mma.sync.aligned.m16n8k16.row.col.f32.bf16.bf16.f32 "
        "{%0,%1,%2,%3}, {%4,%5,%6,%7}, {%8,%9}, {%0,%1,%2,%3};"
        : "+f"(d[0]), "+f"(d[1]), "+f"(d[2]), "+f"(d[3])
        : "r"(a[0]), "r"(a[1]), "r"(a[2]), "r"(a[3]), "r"(b0), "r"(b1));
}
__device__ __forceinline__ float ex2(float x) {
    float y;
    asm("ex2.approx.f32 %0, %1;" : "=f"(y) : "f"(x));
    return y;
}
__device__ __forceinline__ void split2(float v, bf16* H, bf16* L, size_t o) {
    bf16 hb = __float2bfloat16(v);
    H[o] = hb;
    L[o] = __float2bfloat16(v - __bfloat162float(hb));
}
// swizzle for 64B-wide rows (GEMM tiles)
__device__ __forceinline__ uint32_t sw64(int row, int c16) {
    return (uint32_t)(row * 64 + ((c16 ^ ((row >> 1) & 3)) << 4));
}
// standard 128B swizzle for 128B-wide rows (flash tiles)
__device__ __forceinline__ uint32_t sw128(uint32_t off) {
    return off ^ ((off >> 3) & 0x70);
}

// ======================= HMMA bf16-split GEMM (R11 config) =======================
// C = (Ah+Al)[M,K] @ (Bh+Bl)[N,K]^T.  128x128 tile, BK=32, 256 thr (8 warps 2x4),
// warp tile 64x32, 3-stage cp.async, 64B swizzle.
// EPI=0: write fp32 C.  EPI=1: fused rope/split/transpose epilogue for qkv.
template <int EPI>
__global__ __launch_bounds__(256)
void mma_gemm_kernel(const bf16* __restrict__ Ah, const bf16* __restrict__ Al,
                     const bf16* __restrict__ Bh, const bf16* __restrict__ Bl,
                     float* __restrict__ C, int K, int ldC,
                     const float* __restrict__ cs,
                     bf16* __restrict__ Qh, bf16* __restrict__ Ql,
                     bf16* __restrict__ Kh, bf16* __restrict__ Kl,
                     bf16* __restrict__ Vth, bf16* __restrict__ Vtl) {
    constexpr int ABYTES = 128 * 64;   // 8192
    constexpr int BBYTES = 128 * 64;
    constexpr int STAGE  = 2 * ABYTES + 2 * BBYTES;   // 32768

    extern __shared__ char smem[];
    uint32_t sb = smem_to_u32(smem);

    int tid = threadIdx.x;
    int lane = tid & 31, wid = tid >> 5;
    int wm = wid & 1, wn = wid >> 1;      // 2x4 warp grid, warp tile 64x32

    int n0 = blockIdx.x * 128;
    int m0 = blockIdx.y * 128;

    float acc[4][4][4];
#pragma unroll
    for (int i = 0; i < 4; i++)
#pragma unroll
        for (int j = 0; j < 4; j++)
#pragma unroll
            for (int c = 0; c < 4; c++) acc[i][j][c] = 0.f;

    const int nkt = K >> 5;

    auto load_tiles = [&](int kt, int buf) {
        uint32_t base = sb + buf * STAGE;
#pragma unroll
        for (int it = 0; it < 2; it++) {
            int i = tid + it * 256;
            int r = i >> 2, c = i & 3;
            size_t g = (size_t)(m0 + r) * K + (size_t)kt * 32 + c * 8;
            uint32_t so = base + sw64(r, c);
            cp16(so, Ah + g);
            cp16(so + ABYTES, Al + g);
        }
#pragma unroll
        for (int it = 0; it < 2; it++) {
            int i = tid + it * 256;
            int r = i >> 2, c = i & 3;
            size_t g = (size_t)(n0 + r) * K + (size_t)kt * 32 + c * 8;
            uint32_t so = base + 2 * ABYTES + sw64(r, c);
            cp16(so, Bh + g);
            cp16(so + BBYTES, Bl + g);
        }
    };

    load_tiles(0, 0);
    asm volatile("cp.async.commit_group;" ::: "memory");
    if (nkt > 1) {
        load_tiles(1, 1);
        asm volatile("cp.async.commit_group;" ::: "memory");
    }

    int stage = 0;
    for (int kt = 0; kt < nkt; kt++) {
        if (kt < nkt - 1) {
            asm volatile("cp.async.wait_group 1;" ::: "memory");
        } else {
            asm volatile("cp.async.wait_group 0;" ::: "memory");
        }
        __syncthreads();

        if (kt + 2 < nkt) {
            int nb = stage + 2; if (nb >= 3) nb -= 3;
            load_tiles(kt + 2, nb);
            asm volatile("cp.async.commit_group;" ::: "memory");
        }

        uint32_t abase = sb + stage * STAGE;
        uint32_t bbase = abase + 2 * ABYTES;

#pragma unroll
        for (int ks = 0; ks < 2; ks++) {
            int arow = wm * 64 + (lane & 15);
            int c16  = ks * 2 + (lane >> 4);

            uint32_t ah[4][4], al[4][4];
#pragma unroll
            for (int i = 0; i < 4; i++) {
                uint32_t ad = abase + sw64(arow + i * 16, c16);
                ldm_x4(ah[i], ad);
                ldm_x4(al[i], ad + ABYTES);
            }

            uint32_t bh[2][4], bl[2][4];
            int brow = wn * 32 + (lane & 15);
#pragma unroll
            for (int g = 0; g < 2; g++) {
                uint32_t bd = bbase + sw64(brow + g * 16, c16);
                ldm_x4(bh[g], bd);
                ldm_x4(bl[g], bd + BBYTES);
            }

#pragma unroll
            for (int i = 0; i < 4; i++)
#pragma unroll
                for (int j = 0; j < 4; j++) {
                    int g = j >> 1, hf = j & 1;
                    uint32_t b0h = bh[g][hf], b1h = bh[g][hf + 2];
                    uint32_t b0l = bl[g][hf], b1l = bl[g][hf + 2];
                    mma16816(acc[i][j], ah[i], b0h, b1h);
                    mma16816(acc[i][j], ah[i], b0l, b1l);
                    mma16816(acc[i][j], al[i], b0h, b1h);
                }
        }
        if (++stage == 3) stage = 0;
    }

    int r0 = lane >> 2, c0 = (lane & 3) * 2;

    if (EPI == 0) {
#pragma unroll
        for (int i = 0; i < 4; i++) {
            int row = m0 + wm * 64 + i * 16 + r0;
#pragma unroll
            for (int j = 0; j < 4; j++) {
                int col = n0 + wn * 32 + j * 8 + c0;
                *(float2*)&C[(size_t)row * ldC + col] =
                    make_float2(acc[i][j][0], acc[i][j][1]);
                *(float2*)&C[(size_t)(row + 8) * ldC + col] =
                    make_float2(acc[i][j][2], acc[i][j][3]);
            }
        }
        return;
    }

    // ===== fused qkv epilogue: stage acc tile through smem (128 x 129 f32) =====
    __syncthreads();
    float* st = (float*)smem;
#pragma unroll
    for (int i = 0; i < 4; i++) {
        int row = wm * 64 + i * 16 + r0;
#pragma unroll
        for (int j = 0; j < 4; j++) {
            int col = wn * 32 + j * 8 + c0;
            st[row * 129 + col]           = acc[i][j][0];
            st[row * 129 + col + 1]       = acc[i][j][1];
            st[(row + 8) * 129 + col]     = acc[i][j][2];
            st[(row + 8) * 129 + col + 1] = acc[i][j][3];
        }
    }
    __syncthreads();

    int mt = n0 >> 10;                // 0=q, 1=k, 2=v
    int h0 = (n0 & 1023) >> 6;        // first head in this tile (even)
    int nbase = m0 & 2047;
    int bb = m0 >> 11;

    if (mt < 2) {
        // RoPE + split into Q or K, [bh, n, 64]
        int i  = tid & 31;
        int hh = (tid >> 5) & 1;
        int rg = tid >> 6;            // 4 row groups of 32
        bf16* Hh = (mt == 0) ? Qh : Kh;
        bf16* Hl = (mt == 0) ? Ql : Kl;
        const float sc = (mt == 0) ? 0.125f * 1.44269504089f : 1.0f;
        size_t bhb = ((size_t)(bb * HH + h0 + hh)) * NN;
        int hcol = hh * 64;
#pragma unroll 4
        for (int rr = 0; rr < 32; rr++) {
            int r = rg * 32 + rr;
            int n = nbase + r;
            float v1 = st[r * 129 + hcol + i];
            float v2 = st[r * 129 + hcol + i + 32];
            float2 csv = *(const float2*)&cs[(n * 32 + i) * 2];
            float a1 = sc * (v1 * csv.x - v2 * csv.y);
            float a2 = sc * (v2 * csv.x + v1 * csv.y);
            size_t ob = (bhb + n) * 64;
            split2(a1, Hh, Hl, ob + i);
            split2(a2, Hh, Hl, ob + i + 32);
        }
    } else {
        // V transpose + split into Vt [bh, d, n]
        int hh = tid >> 7;            // 0..1
        int dh = (tid >> 6) & 1;      // d half
        int np = (tid & 63) * 2;      // row pair
        size_t vb = ((size_t)(bb * HH + h0 + hh)) * 64;
        int hcol = hh * 64;
#pragma unroll 4
        for (int dd = 0; dd < 32; dd++) {
            int d = dh * 32 + dd;
            float v0 = st[np * 129 + hcol + d];
            float v1 = st[(np + 1) * 129 + hcol + d];
            __nv_bfloat162 hv = __floats2bfloat162_rn(v0, v1);
            __nv_bfloat162 lv = __floats2bfloat162_rn(v0 - __bfloat162float(hv.x),
                                                      v1 - __bfloat162float(hv.y));
            size_t off = (vb + d) * NN + nbase + np;
            *(__nv_bfloat162*)&Vth[off] = hv;
            *(__nv_bfloat162*)&Vtl[off] = lv;
        }
    }
}

// ======================= fused flash attention (HMMA, bf16-split) ==============
// Per CTA: 64 q rows of one (b,h), 4 warps x 16 rows, 128 threads, 128B swizzle.
// V-fragment LDSMs hoisted above exp/pack so smem latency overlaps MUFU/ALU chains.
__global__ __launch_bounds__(128, 3)
void flash_kernel(const bf16* __restrict__ Qh_, const bf16* __restrict__ Ql_,
                  const bf16* __restrict__ Kh_, const bf16* __restrict__ Kl_,
                  const bf16* __restrict__ Vh_, const bf16* __restrict__ Vl_,
                  bf16* __restrict__ aOh, bf16* __restrict__ aOl) {
    constexpr int FTILE = 8192;       // 64 rows x 128B, swizzled
    constexpr int FSTG  = 4 * FTILE;  // Kh,Kl,Vh,Vl

    extern __shared__ char smem[];
    uint32_t sb = smem_to_u32(smem);
    int tid = threadIdx.x, lane = tid & 31, wid = tid >> 5;
    int q0 = blockIdx.x * 64;
    int bh = blockIdx.y;
    int b = bh >> 4, h = bh & 15;

    const bf16* Qhp = Qh_ + ((size_t)bh * NN + q0) * 64;
    const bf16* Qlp = Ql_ + ((size_t)bh * NN + q0) * 64;
    const bf16* Khp = Kh_ + (size_t)bh * NN * 64;
    const bf16* Klp = Kl_ + (size_t)bh * NN * 64;
    const bf16* Vhp = Vh_ + (size_t)bh * 64 * NN;
    const bf16* Vlp = Vl_ + (size_t)bh * 64 * NN;

#pragma unroll
    for (int it = 0; it < 4; it++) {
        int i = tid + it * 128;
        int r = i >> 3, c = i & 7;
        uint32_t so = sw128((uint32_t)(r * 128 + c * 16));
        cp16(sb + so, Qhp + r * 64 + c * 8);
        cp16(sb + FTILE + so, Qlp + r * 64 + c * 8);
    }
    asm volatile("cp.async.commit_group;" ::: "memory");

    auto load_kv = [&](int kt, int buf) {
        uint32_t base = sb + buf * FSTG;
        int kv0 = kt * 64;
#pragma unroll
        for (int it = 0; it < 16; it++) {
            int i = tid + it * 128;
            int mat = i >> 9;
            int slot = i & 511;
            int r = slot >> 3, c = slot & 7;
            uint32_t so = base + mat * FTILE + sw128((uint32_t)(r * 128 + c * 16));
            const bf16* g;
            if (mat == 0)      g = Khp + (size_t)(kv0 + r) * 64 + c * 8;
            else if (mat == 1) g = Klp + (size_t)(kv0 + r) * 64 + c * 8;
            else if (mat == 2) g = Vhp + (size_t)r * NN + kv0 + c * 8;
            else               g = Vlp + (size_t)r * NN + kv0 + c * 8;
            cp16(so, g);
        }
    };

    load_kv(0, 1);
    asm volatile("cp.async.commit_group;" ::: "memory");
    asm volatile("cp.async.wait_group 1;" ::: "memory");
    __syncthreads();

    uint32_t qh[4][4], ql[4][4];
    {
        int arow = wid * 16 + (lane & 15);
#pragma unroll
        for (int ks = 0; ks < 4; ks++) {
            int c16 = ks * 2 + (lane >> 4);
            uint32_t so = sw128((uint32_t)(arow * 128 + c16 * 16));
            ldm_x4(qh[ks], sb + so);
            ldm_x4(ql[ks], sb + FTILE + so);
        }
    }
    __syncthreads();

    float o[8][4];
#pragma unroll
    for (int j = 0; j < 8; j++)
#pragma unroll
        for (int c = 0; c < 4; c++) o[j][c] = 0.f;
    float lpart[2] = {0.f, 0.f};

    for (int kt = 0; kt < NN / 64; kt++) {
        int cur = (kt + 1) & 1;
        if (kt + 1 < NN / 64) {
            load_kv(kt + 1, kt & 1);
            asm volatile("cp.async.commit_group;" ::: "memory");
            asm volatile("cp.async.wait_group 1;" ::: "memory");
        } else {
            asm volatile("cp.async.wait_group 0;" ::: "memory");
        }
        __syncthreads();

        uint32_t kb = sb + cur * FSTG;
        uint32_t vb = kb + 2 * FTILE;

        // ---- S = Q @ K^T (0.125*log2e pre-folded into Q) ----
        float s[8][4];
#pragma unroll
        for (int j = 0; j < 8; j++)
#pragma unroll
            for (int c = 0; c < 4; c++) s[j][c] = 0.f;
        {
            int brow = lane & 15;
#pragma unroll
            for (int ks = 0; ks < 4; ks++) {
                int c16 = ks * 2 + (lane >> 4);
                uint32_t khf[4][4], klf[4][4];
#pragma unroll
                for (int g = 0; g < 4; g++) {
                    uint32_t so = sw128((uint32_t)((g * 16 + brow) * 128 + c16 * 16));
                    ldm_x4(khf[g], kb + so);
                    ldm_x4(klf[g], kb + FTILE + so);
                }
#pragma unroll
                for (int g = 0; g < 4; g++)
#pragma unroll
                    for (int hf = 0; hf < 2; hf++) {
                        int j = g * 2 + hf;
                        mma16816(s[j], qh[ks], khf[g][hf], khf[g][hf + 2]);
                        mma16816(s[j], qh[ks], klf[g][hf], klf[g][hf + 2]);
                        mma16816(s[j], ql[ks], khf[g][hf], khf[g][hf + 2]);
                    }
            }
        }

        // ---- per-kc: V LDSM first (latency overlaps exp/pack), then PV ----
        {
            int vrow = lane & 15;
#pragma unroll
            for (int kc = 0; kc < 4; kc++) {
                uint32_t vhf[4][4], vlf[4][4];
#pragma unroll
                for (int g = 0; g < 4; g++) {
                    int c16 = kc * 2 + (lane >> 4);
                    uint32_t so = sw128((uint32_t)((g * 16 + vrow) * 128 + c16 * 16));
                    ldm_x4(vhf[g], vb + so);
                    ldm_x4(vlf[g], vb + FTILE + so);
                }

                uint32_t pa[4], pl[4];
#pragma unroll
                for (int t = 0; t < 2; t++) {
                    int j = kc * 2 + t;
#pragma unroll
                    for (int e = 0; e < 4; e++) s[j][e] = ex2(s[j][e]);
                    lpart[0] += s[j][0] + s[j][1];
                    lpart[1] += s[j][2] + s[j][3];
#pragma unroll
                    for (int e = 0; e < 2; e++) {
                        float x = s[j][e * 2], y = s[j][e * 2 + 1];
                        __nv_bfloat162 hv = __floats2bfloat162_rn(x, y);
                        float lx = x - __bfloat162float(hv.x);
                        float ly = y - __bfloat162float(hv.y);
                        __nv_bfloat162 lv = __floats2bfloat162_rn(lx, ly);
                        pa[t * 2 + e] = *(uint32_t*)&hv;
                        pl[t * 2 + e] = *(uint32_t*)&lv;
                    }
                }

#pragma unroll
                for (int g = 0; g < 4; g++)
#pragma unroll
                    for (int hf = 0; hf < 2; hf++) {
                        int dj = g * 2 + hf;
                        mma16816(o[dj], pa, vhf[g][hf], vhf[g][hf + 2]);
                        mma16816(o[dj], pl, vhf[g][hf], vhf[g][hf + 2]);
                        mma16816(o[dj], pa, vlf[g][hf], vlf[g][hf + 2]);
                    }
            }
        }
        __syncthreads();
    }

    // ---- epilogue: reduce row sums, normalize, split, write ----
    float lrow[2];
#pragma unroll
    for (int half = 0; half < 2; half++) {
        float rs = lpart[half];
        rs += __shfl_xor_sync(0xffffffffu, rs, 1);
        rs += __shfl_xor_sync(0xffffffffu, rs, 2);
        lrow[half] = rs;
    }
    float inv0 = 1.f / lrow[0], inv1 = 1.f / lrow[1];
    int r0 = q0 + wid * 16 + (lane >> 2);
    int cb = (lane & 3) * 2;
    size_t row0 = ((size_t)b * NN + r0) * 1024 + h * 64;
    size_t row1 = row0 + (size_t)8 * 1024;
#pragma unroll
    for (int dj = 0; dj < 8; dj++) {
        int col = dj * 8 + cb;
        float v0 = o[dj][0] * inv0, v1 = o[dj][1] * inv0;
        __nv_bfloat162 hv = __floats2bfloat162_rn(v0, v1);
        __nv_bfloat162 lv = __floats2bfloat162_rn(v0 - __bfloat162float(hv.x),
                                                  v1 - __bfloat162float(hv.y));
        *(__nv_bfloat162*)&aOh[row0 + col] = hv;
        *(__nv_bfloat162*)&aOl[row0 + col] = lv;
        float v2 = o[dj][2] * inv1, v3 = o[dj][3] * inv1;
        hv = __floats2bfloat162_rn(v2, v3);
        lv = __floats2bfloat162_rn(v2 - __bfloat162float(hv.x),
                                   v3 - __bfloat162float(hv.y));
        *(__nv_bfloat162*)&aOh[row1 + col] = hv;
        *(__nv_bfloat162*)&aOl[row1 + col] = lv;
    }
}

// ======================= small kernels (separate launches, as in R11) ==========
__global__ void rope_table_kernel(float* __restrict__ cs) {
    int idx = blockIdx.x * blockDim.x + threadIdx.x;
    if (idx >= NN * 32) return;
    int n = idx >> 5, i = idx & 31;
    // fp32 path — matches the reference's own fp32 inv_freq/cos/sin computation
    float inv = powf(10000.0f, -(float)i / 32.0f);
    float ang = (float)n * inv;
    float sv, cv;
    sincosf(ang, &sv, &cv);
    cs[idx * 2]     = cv;
    cs[idx * 2 + 1] = sv;
}

__global__ void split_kernel(const float* __restrict__ src, bf16* __restrict__ H,
                             bf16* __restrict__ L, int n) {
    int i = (blockIdx.x * blockDim.x + threadIdx.x) * 4;
    if (i >= n) return;
    float4 v = *(const float4*)(src + i);
    __nv_bfloat162 h0 = __floats2bfloat162_rn(v.x, v.y);
    __nv_bfloat162 h1 = __floats2bfloat162_rn(v.z, v.w);
    __nv_bfloat162 l0 = __floats2bfloat162_rn(v.x - __bfloat162float(h0.x),
                                              v.y - __bfloat162float(h0.y));
    __nv_bfloat162 l1 = __floats2bfloat162_rn(v.z - __bfloat162float(h1.x),
                                              v.w - __bfloat162float(h1.y));
    *(__nv_bfloat162*)&H[i]     = h0;
    *(__nv_bfloat162*)&H[i + 2] = h1;
    *(__nv_bfloat162*)&L[i]     = l0;
    *(__nv_bfloat162*)&L[i + 2] = l1;
}

__global__ __launch_bounds__(256)
void wtrans_kernel(const float* __restrict__ W, bf16* __restrict__ Th,
                   bf16* __restrict__ Tl, int K, int N) {
    __shared__ float t[32][33];
    int n0 = blockIdx.x * 32, k0 = blockIdx.y * 32;
    int tx = threadIdx.x, ty = threadIdx.y;
#pragma unroll
    for (int s = 0; s < 32; s += 8)
        t[ty + s][tx] = W[(size_t)(k0 + ty + s) * N + n0 + tx];
    __syncthreads();
#pragma unroll
    for (int s = 0; s < 32; s += 8) {
        float v = t[tx][ty + s];
        split2(v, Th, Tl, (size_t)(n0 + ty + s) * K + k0 + tx);
    }
}

// ======================= launch =======================
extern "C" void kernel_launch(void* const* d_in, const int* in_sizes, int n_in,
                              void* d_out, int out_size) {
    const float* x     = (const float*)d_in[0];
    const float* w_qkv = (const float*)d_in[1];
    const float* w_out = (const float*)d_in[2];
    float* out = (float*)d_out;

    float *cs;
    bf16 *xh, *xl, *wqTh, *wqTl, *woTh, *woTl;
    bf16 *Qh, *Ql, *Kh, *Kl, *Vth, *Vtl, *aOh, *aOl;
    cudaGetSymbolAddress((void**)&cs,  g_cs);
    cudaGetSymbolAddress((void**)&xh,  g_xh);   cudaGetSymbolAddress((void**)&xl,  g_xl);
    cudaGetSymbolAddress((void**)&wqTh, g_wqTh); cudaGetSymbolAddress((void**)&wqTl, g_wqTl);
    cudaGetSymbolAddress((void**)&woTh, g_woTh); cudaGetSymbolAddress((void**)&woTl, g_woTl);
    cudaGetSymbolAddress((void**)&Qh, g_Qh);    cudaGetSymbolAddress((void**)&Ql, g_Ql);
    cudaGetSymbolAddress((void**)&Kh, g_Kh);    cudaGetSymbolAddress((void**)&Kl, g_Kl);
    cudaGetSymbolAddress((void**)&Vth, g_Vth);  cudaGetSymbolAddress((void**)&Vtl, g_Vtl);
    cudaGetSymbolAddress((void**)&aOh, g_aOh);  cudaGetSymbolAddress((void**)&aOl, g_aOl);

    const int SMEM_GEMM = 3 * 32768;       // 98304 (>= 128*129*4 for epilogue)
    const int FLASH_SMEM = 2 * 4 * 8192;   // 65536
    cudaFuncSetAttribute(mma_gemm_kernel<0>,
                         cudaFuncAttributeMaxDynamicSharedMemorySize, SMEM_GEMM);
    cudaFuncSetAttribute(mma_gemm_kernel<1>,
                         cudaFuncAttributeMaxDynamicSharedMemorySize, SMEM_GEMM);
    cudaFuncSetAttribute(flash_kernel,
                         cudaFuncAttributeMaxDynamicSharedMemorySize, FLASH_SMEM);

    // 0) rope table + split input / transpose weights (separate launches)
    rope_table_kernel<<<(NN * 32 + 255) / 256, 256>>>(cs);
    split_kernel<<<(MTOT * 1024 / 4 + 255) / 256, 256>>>(x, xh, xl, MTOT * 1024);
    wtrans_kernel<<<dim3(3072 / 32, 1024 / 32), dim3(32, 8)>>>(w_qkv, wqTh, wqTl, 1024, 3072);
    wtrans_kernel<<<dim3(1024 / 32, 1024 / 32), dim3(32, 8)>>>(w_out, woTh, woTl, 1024, 1024);

    // 1) qkv GEMM with fused rope/split/transpose epilogue
    mma_gemm_kernel<1><<<dim3(3072 / 128, 4096 / 128), 256, SMEM_GEMM>>>(
        xh, xl, wqTh, wqTl, nullptr, 1024, 0,
        cs, Qh, Ql, Kh, Kl, Vth, Vtl);

    // 2) fused flash attention -> aOh/aOl [B*N, 1024]
    flash_kernel<<<dim3(NN / 64, BHT), 128, FLASH_SMEM>>>(
        Qh, Ql, Kh, Kl, Vth, Vtl, aOh, aOl);

    // 3) out = aO @ w_out  (M=4096, N=1024, K=1024)
    mma_gemm_kernel<0><<<dim3(1024 / 128, 4096 / 128), 256, SMEM_GEMM>>>(
        aOh, aOl, woTh, woTl, out, 1024, 1024,
        nullptr, nullptr, nullptr, nullptr, nullptr, nullptr, nullptr);
}

// round 16
// speedup vs baseline: 1.0981x; 1.0392x over previous
#include <cuda_runtime.h>
#include <cuda_bf16.h>
#include <math.h>
#include <stdint.h>

typedef __nv_bfloat16 bf16;

#define BB 2
#define NN 2048
#define HH 16
#define MTOT (BB*NN)          // 4096
#define BHT (BB*HH)           // 32

// ======================= scratch (no cudaMalloc allowed) =======================
__device__ __align__(256) bf16  g_xh[(size_t)MTOT * 1024];
__device__ __align__(256) bf16  g_xl[(size_t)MTOT * 1024];
__device__ __align__(256) bf16  g_wqTh[(size_t)3072 * 1024];
__device__ __align__(256) bf16  g_wqTl[(size_t)3072 * 1024];
__device__ __align__(256) bf16  g_woTh[(size_t)1024 * 1024];
__device__ __align__(256) bf16  g_woTl[(size_t)1024 * 1024];
__device__ __align__(256) bf16  g_Qh[(size_t)BHT * NN * 64];
__device__ __align__(256) bf16  g_Ql[(size_t)BHT * NN * 64];
__device__ __align__(256) bf16  g_Kh[(size_t)BHT * NN * 64];
__device__ __align__(256) bf16  g_Kl[(size_t)BHT * NN * 64];
__device__ __align__(256) bf16  g_Vth[(size_t)BHT * 64 * NN];   // [bh, d, n]
__device__ __align__(256) bf16  g_Vtl[(size_t)BHT * 64 * NN];
__device__ __align__(256) bf16  g_aOh[(size_t)MTOT * 1024];
__device__ __align__(256) bf16  g_aOl[(size_t)MTOT * 1024];
__device__ __align__(256) float g_cs[(size_t)NN * 32 * 2];      // rope cos/sin table

// ======================= helpers =======================
__device__ __forceinline__ uint32_t smem_to_u32(const void* p) {
    uint32_t a;
    asm("{ .reg .u64 t; cvta.to.shared.u64 t, %1; cvt.u32.u64 %0, t; }" : "=r"(a) : "l"(p));
    return a;
}
__device__ __forceinline__ void cp16(uint32_t s, const void* g) {
    asm volatile("cp.async.cg.shared.global [%0], [%1], 16;" :: "r"(s), "l"(g) : "memory");
}
__device__ __forceinline__ void ldm_x4(uint32_t* r, uint32_t addr) {
    asm volatile("ldmatrix.sync.aligned.m8n8.x4.shared.b16 {%0,%1,%2,%3}, [%4];"
                 : "=r"(r[0]), "=r"(r[1]), "=r"(r[2]), "=r"(r[3]) : "r"(addr));
}
__device__ __forceinline__ void mma16816(float* d, const uint32_t* a,
                                         uint32_t b0, uint32_t b1) {
    asm volatile(
        "mma.sync.aligned.m16n8k16.row.col.f32.bf16.bf16.f32 "
        "{%0,%1,%2,%3}, {%4,%5,%6,%7}, {%8,%9}, {%0,%1,%2,%3};"
        : "+f"(d[0]), "+f"(d[1]), "+f"(d[2]), "+f"(d[3])
        : "r"(a[0]), "r"(a[1]), "r"(a[2]), "r"(a[3]), "r"(b0), "r"(b1));
}
__device__ __forceinline__ float ex2(float x) {
    float y;
    asm("ex2.approx.f32 %0, %1;" : "=f"(y) : "f"(x));
    return y;
}
__device__ __forceinline__ void split2(float v, bf16* H, bf16* L, size_t o) {
    bf16 hb = __float2bfloat16(v);
    H[o] = hb;
    L[o] = __float2bfloat16(v - __bfloat162float(hb));
}
// swizzle for 64B-wide rows (GEMM tiles)
__device__ __forceinline__ uint32_t sw64(int row, int c16) {
    return (uint32_t)(row * 64 + ((c16 ^ ((row >> 1) & 3)) << 4));
}
// standard 128B swizzle for 128B-wide rows (flash tiles)
__device__ __forceinline__ uint32_t sw128(uint32_t off) {
    return off ^ ((off >> 3) & 0x70);
}

// ======================= HMMA bf16-split GEMM (occ-3 config) ====================
// C = (Ah+Al)[M,K] @ (Bh+Bl)[N,K]^T.  CTA tile 128x64, BK=32, 128 thr (4 warps
// 2x2, warp tile 64x32 — same inner loop as before), 3-stage cp.async.
// 3 CTAs/SM -> 3 warps/SMSP, matching the flash kernel's winning depth.
// EPI=0: write fp32 C.  EPI=1: fused rope/split/transpose epilogue (one head/tile).
template <int EPI>
__global__ __launch_bounds__(128, 3)
void mma_gemm_kernel(const bf16* __restrict__ Ah, const bf16* __restrict__ Al,
                     const bf16* __restrict__ Bh, const bf16* __restrict__ Bl,
                     float* __restrict__ C, int K, int ldC,
                     const float* __restrict__ cs,
                     bf16* __restrict__ Qh, bf16* __restrict__ Ql,
                     bf16* __restrict__ Kh, bf16* __restrict__ Kl,
                     bf16* __restrict__ Vth, bf16* __restrict__ Vtl) {
    constexpr int ABYTES = 128 * 64;   // 8192
    constexpr int BBYTES = 64 * 64;    // 4096
    constexpr int STAGE  = 2 * ABYTES + 2 * BBYTES;   // 24576

    extern __shared__ char smem[];
    uint32_t sb = smem_to_u32(smem);

    int tid = threadIdx.x;
    int lane = tid & 31, wid = tid >> 5;
    int wm = wid & 1, wn = wid >> 1;      // 2x2 warp grid, warp tile 64x32

    int n0 = blockIdx.x * 64;
    int m0 = blockIdx.y * 128;

    float acc[4][4][4];
#pragma unroll
    for (int i = 0; i < 4; i++)
#pragma unroll
        for (int j = 0; j < 4; j++)
#pragma unroll
            for (int c = 0; c < 4; c++) acc[i][j][c] = 0.f;

    const int nkt = K >> 5;

    auto load_tiles = [&](int kt, int buf) {
        uint32_t base = sb + buf * STAGE;
#pragma unroll
        for (int it = 0; it < 4; it++) {
            int i = tid + it * 128;          // 512 A slots
            int r = i >> 2, c = i & 3;
            size_t g = (size_t)(m0 + r) * K + (size_t)kt * 32 + c * 8;
            uint32_t so = base + sw64(r, c);
            cp16(so, Ah + g);
            cp16(so + ABYTES, Al + g);
        }
#pragma unroll
        for (int it = 0; it < 2; it++) {
            int i = tid + it * 128;          // 256 B slots
            int r = i >> 2, c = i & 3;
            size_t g = (size_t)(n0 + r) * K + (size_t)kt * 32 + c * 8;
            uint32_t so = base + 2 * ABYTES + sw64(r, c);
            cp16(so, Bh + g);
            cp16(so + BBYTES, Bl + g);
        }
    };

    load_tiles(0, 0);
    asm volatile("cp.async.commit_group;" ::: "memory");
    if (nkt > 1) {
        load_tiles(1, 1);
        asm volatile("cp.async.commit_group;" ::: "memory");
    }

    int stage = 0;
    for (int kt = 0; kt < nkt; kt++) {
        if (kt < nkt - 1) {
            asm volatile("cp.async.wait_group 1;" ::: "memory");
        } else {
            asm volatile("cp.async.wait_group 0;" ::: "memory");
        }
        __syncthreads();

        if (kt + 2 < nkt) {
            int nb = stage + 2; if (nb >= 3) nb -= 3;
            load_tiles(kt + 2, nb);
            asm volatile("cp.async.commit_group;" ::: "memory");
        }

        uint32_t abase = sb + stage * STAGE;
        uint32_t bbase = abase + 2 * ABYTES;

#pragma unroll
        for (int ks = 0; ks < 2; ks++) {
            int arow = wm * 64 + (lane & 15);
            int c16  = ks * 2 + (lane >> 4);

            uint32_t ah[4][4], al[4][4];
#pragma unroll
            for (int i = 0; i < 4; i++) {
                uint32_t ad = abase + sw64(arow + i * 16, c16);
                ldm_x4(ah[i], ad);
                ldm_x4(al[i], ad + ABYTES);
            }

            uint32_t bh[2][4], bl[2][4];
            int brow = wn * 32 + (lane & 15);
#pragma unroll
            for (int g = 0; g < 2; g++) {
                uint32_t bd = bbase + sw64(brow + g * 16, c16);
                ldm_x4(bh[g], bd);
                ldm_x4(bl[g], bd + BBYTES);
            }

#pragma unroll
            for (int i = 0; i < 4; i++)
#pragma unroll
                for (int j = 0; j < 4; j++) {
                    int g = j >> 1, hf = j & 1;
                    uint32_t b0h = bh[g][hf], b1h = bh[g][hf + 2];
                    uint32_t b0l = bl[g][hf], b1l = bl[g][hf + 2];
                    mma16816(acc[i][j], ah[i], b0h, b1h);
                    mma16816(acc[i][j], ah[i], b0l, b1l);
                    mma16816(acc[i][j], al[i], b0h, b1h);
                }
        }
        if (++stage == 3) stage = 0;
    }

    int r0 = lane >> 2, c0 = (lane & 3) * 2;

    if (EPI == 0) {
#pragma unroll
        for (int i = 0; i < 4; i++) {
            int row = m0 + wm * 64 + i * 16 + r0;
#pragma unroll
            for (int j = 0; j < 4; j++) {
                int col = n0 + wn * 32 + j * 8 + c0;
                *(float2*)&C[(size_t)row * ldC + col] =
                    make_float2(acc[i][j][0], acc[i][j][1]);
                *(float2*)&C[(size_t)(row + 8) * ldC + col] =
                    make_float2(acc[i][j][2], acc[i][j][3]);
            }
        }
        return;
    }

    // ===== fused qkv epilogue: one head per tile; stage through smem 128x65 f32 ==
    __syncthreads();
    float* st = (float*)smem;
#pragma unroll
    for (int i = 0; i < 4; i++) {
        int row = wm * 64 + i * 16 + r0;
#pragma unroll
        for (int j = 0; j < 4; j++) {
            int col = wn * 32 + j * 8 + c0;
            st[row * 65 + col]           = acc[i][j][0];
            st[row * 65 + col + 1]       = acc[i][j][1];
            st[(row + 8) * 65 + col]     = acc[i][j][2];
            st[(row + 8) * 65 + col + 1] = acc[i][j][3];
        }
    }
    __syncthreads();

    int mt = n0 >> 10;                // 0=q, 1=k, 2=v
    int h0 = (n0 & 1023) >> 6;        // the single head of this tile
    int nbase = m0 & 2047;
    int bb = m0 >> 11;

    if (mt < 2) {
        // RoPE + split into Q or K, [bh, n, 64]
        int i  = tid & 31;
        int rg = tid >> 5;            // 4 row groups of 32
        bf16* Hh = (mt == 0) ? Qh : Kh;
        bf16* Hl = (mt == 0) ? Ql : Kl;
        const float sc = (mt == 0) ? 0.125f * 1.44269504089f : 1.0f;
        size_t bhb = ((size_t)(bb * HH + h0)) * NN;
#pragma unroll 4
        for (int rr = 0; rr < 32; rr++) {
            int r = rg * 32 + rr;
            int n = nbase + r;
            float v1 = st[r * 65 + i];
            float v2 = st[r * 65 + i + 32];
            float2 csv = *(const float2*)&cs[(n * 32 + i) * 2];
            float a1 = sc * (v1 * csv.x - v2 * csv.y);
            float a2 = sc * (v2 * csv.x + v1 * csv.y);
            size_t ob = (bhb + n) * 64;
            split2(a1, Hh, Hl, ob + i);
            split2(a2, Hh, Hl, ob + i + 32);
        }
    } else {
        // V transpose + split into Vt [bh, d, n]
        int dh = tid >> 6;            // d half (0..1)
        int np = (tid & 63) * 2;      // row pair
        size_t vb = ((size_t)(bb * HH + h0)) * 64;
#pragma unroll 4
        for (int dd = 0; dd < 32; dd++) {
            int d = dh * 32 + dd;
            float v0 = st[np * 65 + d];
            float v1 = st[(np + 1) * 65 + d];
            __nv_bfloat162 hv = __floats2bfloat162_rn(v0, v1);
            __nv_bfloat162 lv = __floats2bfloat162_rn(v0 - __bfloat162float(hv.x),
                                                      v1 - __bfloat162float(hv.y));
            size_t off = (vb + d) * NN + nbase + np;
            *(__nv_bfloat162*)&Vth[off] = hv;
            *(__nv_bfloat162*)&Vtl[off] = lv;
        }
    }
}

// ======================= fused flash attention (HMMA, bf16-split) ==============
// Per CTA: 64 q rows of one (b,h), 4 warps x 16 rows, 128 threads, 128B swizzle.
// V-fragment LDSMs hoisted above exp/pack so smem latency overlaps MUFU/ALU chains.
__global__ __launch_bounds__(128, 3)
void flash_kernel(const bf16* __restrict__ Qh_, const bf16* __restrict__ Ql_,
                  const bf16* __restrict__ Kh_, const bf16* __restrict__ Kl_,
                  const bf16* __restrict__ Vh_, const bf16* __restrict__ Vl_,
                  bf16* __restrict__ aOh, bf16* __restrict__ aOl) {
    constexpr int FTILE = 8192;       // 64 rows x 128B, swizzled
    constexpr int FSTG  = 4 * FTILE;  // Kh,Kl,Vh,Vl

    extern __shared__ char smem[];
    uint32_t sb = smem_to_u32(smem);
    int tid = threadIdx.x, lane = tid & 31, wid = tid >> 5;
    int q0 = blockIdx.x * 64;
    int bh = blockIdx.y;
    int b = bh >> 4, h = bh & 15;

    const bf16* Qhp = Qh_ + ((size_t)bh * NN + q0) * 64;
    const bf16* Qlp = Ql_ + ((size_t)bh * NN + q0) * 64;
    const bf16* Khp = Kh_ + (size_t)bh * NN * 64;
    const bf16* Klp = Kl_ + (size_t)bh * NN * 64;
    const bf16* Vhp = Vh_ + (size_t)bh * 64 * NN;
    const bf16* Vlp = Vl_ + (size_t)bh * 64 * NN;

#pragma unroll
    for (int it = 0; it < 4; it++) {
        int i = tid + it * 128;
        int r = i >> 3, c = i & 7;
        uint32_t so = sw128((uint32_t)(r * 128 + c * 16));
        cp16(sb + so, Qhp + r * 64 + c * 8);
        cp16(sb + FTILE + so, Qlp + r * 64 + c * 8);
    }
    asm volatile("cp.async.commit_group;" ::: "memory");

    auto load_kv = [&](int kt, int buf) {
        uint32_t base = sb + buf * FSTG;
        int kv0 = kt * 64;
#pragma unroll
        for (int it = 0; it < 16; it++) {
            int i = tid + it * 128;
            int mat = i >> 9;
            int slot = i & 511;
            int r = slot >> 3, c = slot & 7;
            uint32_t so = base + mat * FTILE + sw128((uint32_t)(r * 128 + c * 16));
            const bf16* g;
            if (mat == 0)      g = Khp + (size_t)(kv0 + r) * 64 + c * 8;
            else if (mat == 1) g = Klp + (size_t)(kv0 + r) * 64 + c * 8;
            else if (mat == 2) g = Vhp + (size_t)r * NN + kv0 + c * 8;
            else               g = Vlp + (size_t)r * NN + kv0 + c * 8;
            cp16(so, g);
        }
    };

    load_kv(0, 1);
    asm volatile("cp.async.commit_group;" ::: "memory");
    asm volatile("cp.async.wait_group 1;" ::: "memory");
    __syncthreads();

    uint32_t qh[4][4], ql[4][4];
    {
        int arow = wid * 16 + (lane & 15);
#pragma unroll
        for (int ks = 0; ks < 4; ks++) {
            int c16 = ks * 2 + (lane >> 4);
            uint32_t so = sw128((uint32_t)(arow * 128 + c16 * 16));
            ldm_x4(qh[ks], sb + so);
            ldm_x4(ql[ks], sb + FTILE + so);
        }
    }
    __syncthreads();

    float o[8][4];
#pragma unroll
    for (int j = 0; j < 8; j++)
#pragma unroll
        for (int c = 0; c < 4; c++) o[j][c] = 0.f;
    float lpart[2] = {0.f, 0.f};

    for (int kt = 0; kt < NN / 64; kt++) {
        int cur = (kt + 1) & 1;
        if (kt + 1 < NN / 64) {
            load_kv(kt + 1, kt & 1);
            asm volatile("cp.async.commit_group;" ::: "memory");
            asm volatile("cp.async.wait_group 1;" ::: "memory");
        } else {
            asm volatile("cp.async.wait_group 0;" ::: "memory");
        }
        __syncthreads();

        uint32_t kb = sb + cur * FSTG;
        uint32_t vb = kb + 2 * FTILE;

        // ---- S = Q @ K^T (0.125*log2e pre-folded into Q) ----
        float s[8][4];
#pragma unroll
        for (int j = 0; j < 8; j++)
#pragma unroll
            for (int c = 0; c < 4; c++) s[j][c] = 0.f;
        {
            int brow = lane & 15;
#pragma unroll
            for (int ks = 0; ks < 4; ks++) {
                int c16 = ks * 2 + (lane >> 4);
                uint32_t khf[4][4], klf[4][4];
#pragma unroll
                for (int g = 0; g < 4; g++) {
                    uint32_t so = sw128((uint32_t)((g * 16 + brow) * 128 + c16 * 16));
                    ldm_x4(khf[g], kb + so);
                    ldm_x4(klf[g], kb + FTILE + so);
                }
#pragma unroll
                for (int g = 0; g < 4; g++)
#pragma unroll
                    for (int hf = 0; hf < 2; hf++) {
                        int j = g * 2 + hf;
                        mma16816(s[j], qh[ks], khf[g][hf], khf[g][hf + 2]);
                        mma16816(s[j], qh[ks], klf[g][hf], klf[g][hf + 2]);
                        mma16816(s[j], ql[ks], khf[g][hf], khf[g][hf + 2]);
                    }
            }
        }

        // ---- per-kc: V LDSM first (latency overlaps exp/pack), then PV ----
        {
            int vrow = lane & 15;
#pragma unroll
            for (int kc = 0; kc < 4; kc++) {
                uint32_t vhf[4][4], vlf[4][4];
#pragma unroll
                for (int g = 0; g < 4; g++) {
                    int c16 = kc * 2 + (lane >> 4);
                    uint32_t so = sw128((uint32_t)((g * 16 + vrow) * 128 + c16 * 16));
                    ldm_x4(vhf[g], vb + so);
                    ldm_x4(vlf[g], vb + FTILE + so);
                }

                uint32_t pa[4], pl[4];
#pragma unroll
                for (int t = 0; t < 2; t++) {
                    int j = kc * 2 + t;
#pragma unroll
                    for (int e = 0; e < 4; e++) s[j][e] = ex2(s[j][e]);
                    lpart[0] += s[j][0] + s[j][1];
                    lpart[1] += s[j][2] + s[j][3];
#pragma unroll
                    for (int e = 0; e < 2; e++) {
                        float x = s[j][e * 2], y = s[j][e * 2 + 1];
                        __nv_bfloat162 hv = __floats2bfloat162_rn(x, y);
                        float lx = x - __bfloat162float(hv.x);
                        float ly = y - __bfloat162float(hv.y);
                        __nv_bfloat162 lv = __floats2bfloat162_rn(lx, ly);
                        pa[t * 2 + e] = *(uint32_t*)&hv;
                        pl[t * 2 + e] = *(uint32_t*)&lv;
                    }
                }

#pragma unroll
                for (int g = 0; g < 4; g++)
#pragma unroll
                    for (int hf = 0; hf < 2; hf++) {
                        int dj = g * 2 + hf;
                        mma16816(o[dj], pa, vhf[g][hf], vhf[g][hf + 2]);
                        mma16816(o[dj], pl, vhf[g][hf], vhf[g][hf + 2]);
                        mma16816(o[dj], pa, vlf[g][hf], vlf[g][hf + 2]);
                    }
            }
        }
        __syncthreads();
    }

    // ---- epilogue: reduce row sums, normalize, split, write ----
    float lrow[2];
#pragma unroll
    for (int half = 0; half < 2; half++) {
        float rs = lpart[half];
        rs += __shfl_xor_sync(0xffffffffu, rs, 1);
        rs += __shfl_xor_sync(0xffffffffu, rs, 2);
        lrow[half] = rs;
    }
    float inv0 = 1.f / lrow[0], inv1 = 1.f / lrow[1];
    int r0 = q0 + wid * 16 + (lane >> 2);
    int cb = (lane & 3) * 2;
    size_t row0 = ((size_t)b * NN + r0) * 1024 + h * 64;
    size_t row1 = row0 + (size_t)8 * 1024;
#pragma unroll
    for (int dj = 0; dj < 8; dj++) {
        int col = dj * 8 + cb;
        float v0 = o[dj][0] * inv0, v1 = o[dj][1] * inv0;
        __nv_bfloat162 hv = __floats2bfloat162_rn(v0, v1);
        __nv_bfloat162 lv = __floats2bfloat162_rn(v0 - __bfloat162float(hv.x),
                                                  v1 - __bfloat162float(hv.y));
        *(__nv_bfloat162*)&aOh[row0 + col] = hv;
        *(__nv_bfloat162*)&aOl[row0 + col] = lv;
        float v2 = o[dj][2] * inv1, v3 = o[dj][3] * inv1;
        hv = __floats2bfloat162_rn(v2, v3);
        lv = __floats2bfloat162_rn(v2 - __bfloat162float(hv.x),
                                   v3 - __bfloat162float(hv.y));
        *(__nv_bfloat162*)&aOh[row1 + col] = hv;
        *(__nv_bfloat162*)&aOl[row1 + col] = lv;
    }
}

// ======================= small kernels (separate launches) =====================
__global__ void rope_table_kernel(float* __restrict__ cs) {
    int idx = blockIdx.x * blockDim.x + threadIdx.x;
    if (idx >= NN * 32) return;
    int n = idx >> 5, i = idx & 31;
    float inv = powf(10000.0f, -(float)i / 32.0f);
    float ang = (float)n * inv;
    float sv, cv;
    sincosf(ang, &sv, &cv);
    cs[idx * 2]     = cv;
    cs[idx * 2 + 1] = sv;
}

__global__ void split_kernel(const float* __restrict__ src, bf16* __restrict__ H,
                             bf16* __restrict__ L, int n) {
    int i = (blockIdx.x * blockDim.x + threadIdx.x) * 4;
    if (i >= n) return;
    float4 v = *(const float4*)(src + i);
    __nv_bfloat162 h0 = __floats2bfloat162_rn(v.x, v.y);
    __nv_bfloat162 h1 = __floats2bfloat162_rn(v.z, v.w);
    __nv_bfloat162 l0 = __floats2bfloat162_rn(v.x - __bfloat162float(h0.x),
                                              v.y - __bfloat162float(h0.y));
    __nv_bfloat162 l1 = __floats2bfloat162_rn(v.z - __bfloat162float(h1.x),
                                              v.w - __bfloat162float(h1.y));
    *(__nv_bfloat162*)&H[i]     = h0;
    *(__nv_bfloat162*)&H[i + 2] = h1;
    *(__nv_bfloat162*)&L[i]     = l0;
    *(__nv_bfloat162*)&L[i + 2] = l1;
}

__global__ __launch_bounds__(256)
void wtrans_kernel(const float* __restrict__ W, bf16* __restrict__ Th,
                   bf16* __restrict__ Tl, int K, int N) {
    __shared__ float t[32][33];
    int n0 = blockIdx.x * 32, k0 = blockIdx.y * 32;
    int tx = threadIdx.x, ty = threadIdx.y;
#pragma unroll
    for (int s = 0; s < 32; s += 8)
        t[ty + s][tx] = W[(size_t)(k0 + ty + s) * N + n0 + tx];
    __syncthreads();
#pragma unroll
    for (int s = 0; s < 32; s += 8) {
        float v = t[tx][ty + s];
        split2(v, Th, Tl, (size_t)(n0 + ty + s) * K + k0 + tx);
    }
}

// ======================= launch =======================
extern "C" void kernel_launch(void* const* d_in, const int* in_sizes, int n_in,
                              void* d_out, int out_size) {
    const float* x     = (const float*)d_in[0];
    const float* w_qkv = (const float*)d_in[1];
    const float* w_out = (const float*)d_in[2];
    float* out = (float*)d_out;

    float *cs;
    bf16 *xh, *xl, *wqTh, *wqTl, *woTh, *woTl;
    bf16 *Qh, *Ql, *Kh, *Kl, *Vth, *Vtl, *aOh, *aOl;
    cudaGetSymbolAddress((void**)&cs,  g_cs);
    cudaGetSymbolAddress((void**)&xh,  g_xh);   cudaGetSymbolAddress((void**)&xl,  g_xl);
    cudaGetSymbolAddress((void**)&wqTh, g_wqTh); cudaGetSymbolAddress((void**)&wqTl, g_wqTl);
    cudaGetSymbolAddress((void**)&woTh, g_woTh); cudaGetSymbolAddress((void**)&woTl, g_woTl);
    cudaGetSymbolAddress((void**)&Qh, g_Qh);    cudaGetSymbolAddress((void**)&Ql, g_Ql);
    cudaGetSymbolAddress((void**)&Kh, g_Kh);    cudaGetSymbolAddress((void**)&Kl, g_Kl);
    cudaGetSymbolAddress((void**)&Vth, g_Vth);  cudaGetSymbolAddress((void**)&Vtl, g_Vtl);
    cudaGetSymbolAddress((void**)&aOh, g_aOh);  cudaGetSymbolAddress((void**)&aOl, g_aOl);

    const int SMEM_GEMM = 3 * 24576;       // 73728 (>= 128*65*4 = 33280 for epilogue)
    const int FLASH_SMEM = 2 * 4 * 8192;   // 65536
    cudaFuncSetAttribute(mma_gemm_kernel<0>,
                         cudaFuncAttributeMaxDynamicSharedMemorySize, SMEM_GEMM);
    cudaFuncSetAttribute(mma_gemm_kernel<1>,
                         cudaFuncAttributeMaxDynamicSharedMemorySize, SMEM_GEMM);
    cudaFuncSetAttribute(flash_kernel,
                         cudaFuncAttributeMaxDynamicSharedMemorySize, FLASH_SMEM);

    // 0) rope table + split input / transpose weights (separate launches)
    rope_table_kernel<<<(NN * 32 + 255) / 256, 256>>>(cs);
    split_kernel<<<(MTOT * 1024 / 4 + 255) / 256, 256>>>(x, xh, xl, MTOT * 1024);
    wtrans_kernel<<<dim3(3072 / 32, 1024 / 32), dim3(32, 8)>>>(w_qkv, wqTh, wqTl, 1024, 3072);
    wtrans_kernel<<<dim3(1024 / 32, 1024 / 32), dim3(32, 8)>>>(w_out, woTh, woTl, 1024, 1024);

    // 1) qkv GEMM with fused rope/split/transpose epilogue (tile 128x64, occ 3)
    mma_gemm_kernel<1><<<dim3(3072 / 64, 4096 / 128), 128, SMEM_GEMM>>>(
        xh, xl, wqTh, wqTl, nullptr, 1024, 0,
        cs, Qh, Ql, Kh, Kl, Vth, Vtl);

    // 2) fused flash attention -> aOh/aOl [B*N, 1024]
    flash_kernel<<<dim3(NN / 64, BHT), 128, FLASH_SMEM>>>(
        Qh, Ql, Kh, Kl, Vth, Vtl, aOh, aOl);

    // 3) out = aO @ w_out  (M=4096, N=1024, K=1024), tile 128x64, occ 3
    mma_gemm_kernel<0><<<dim3(1024 / 64, 4096 / 128), 128, SMEM_GEMM>>>(
        aOh, aOl, woTh, woTl, out, 1024, 1024,
        nullptr, nullptr, nullptr, nullptr, nullptr, nullptr, nullptr);
}

// round 17
// speedup vs baseline: 1.2753x; 1.1614x over previous
#include <cuda_runtime.h>
#include <cuda_bf16.h>
#include <cuda_fp16.h>
#include <math.h>
#include <stdint.h>

typedef __nv_bfloat16 bf16;

#define BB 2
#define NN 2048
#define HH 16
#define MTOT (BB*NN)          // 4096
#define BHT (BB*HH)           // 32

// ======================= scratch (no cudaMalloc allowed) =======================
__device__ __align__(256) __half g_xh[(size_t)MTOT * 1024];
__device__ __align__(256) __half g_xl[(size_t)MTOT * 1024];
__device__ __align__(256) __half g_wqTh[(size_t)3072 * 1024];   // hi-only weights
__device__ __align__(256) __half g_woTh[(size_t)1024 * 1024];
__device__ __align__(256) bf16  g_Qh[(size_t)BHT * NN * 64];
__device__ __align__(256) bf16  g_Ql[(size_t)BHT * NN * 64];
__device__ __align__(256) bf16  g_Kh[(size_t)BHT * NN * 64];
__device__ __align__(256) bf16  g_Kl[(size_t)BHT * NN * 64];
__device__ __align__(256) bf16  g_Vth[(size_t)BHT * 64 * NN];   // [bh, d, n]
__device__ __align__(256) bf16  g_Vtl[(size_t)BHT * 64 * NN];
__device__ __align__(256) __half g_aOh[(size_t)MTOT * 1024];
__device__ __align__(256) __half g_aOl[(size_t)MTOT * 1024];
__device__ __align__(256) float g_cs[(size_t)NN * 32 * 2];      // rope cos/sin table

// ======================= helpers =======================
__device__ __forceinline__ uint32_t smem_to_u32(const void* p) {
    uint32_t a;
    asm("{ .reg .u64 t; cvta.to.shared.u64 t, %1; cvt.u32.u64 %0, t; }" : "=r"(a) : "l"(p));
    return a;
}
__device__ __forceinline__ void cp16(uint32_t s, const void* g) {
    asm volatile("cp.async.cg.shared.global [%0], [%1], 16;" :: "r"(s), "l"(g) : "memory");
}
__device__ __forceinline__ void ldm_x4(uint32_t* r, uint32_t addr) {
    asm volatile("ldmatrix.sync.aligned.m8n8.x4.shared.b16 {%0,%1,%2,%3}, [%4];"
                 : "=r"(r[0]), "=r"(r[1]), "=r"(r[2]), "=r"(r[3]) : "r"(addr));
}
// bf16 mma (flash)
__device__ __forceinline__ void mma16816(float* d, const uint32_t* a,
                                         uint32_t b0, uint32_t b1) {
    asm volatile(
        "mma.sync.aligned.m16n8k16.row.col.f32.bf16.bf16.f32 "
        "{%0,%1,%2,%3}, {%4,%5,%6,%7}, {%8,%9}, {%0,%1,%2,%3};"
        : "+f"(d[0]), "+f"(d[1]), "+f"(d[2]), "+f"(d[3])
        : "r"(a[0]), "r"(a[1]), "r"(a[2]), "r"(a[3]), "r"(b0), "r"(b1));
}
// fp16 mma (projections)
__device__ __forceinline__ void mma16816h(float* d, const uint32_t* a,
                                          uint32_t b0, uint32_t b1) {
    asm volatile(
        "mma.sync.aligned.m16n8k16.row.col.f32.f16.f16.f32 "
        "{%0,%1,%2,%3}, {%4,%5,%6,%7}, {%8,%9}, {%0,%1,%2,%3};"
        : "+f"(d[0]), "+f"(d[1]), "+f"(d[2]), "+f"(d[3])
        : "r"(a[0]), "r"(a[1]), "r"(a[2]), "r"(a[3]), "r"(b0), "r"(b1));
}
__device__ __forceinline__ float ex2(float x) {
    float y;
    asm("ex2.approx.f32 %0, %1;" : "=f"(y) : "f"(x));
    return y;
}
__device__ __forceinline__ void split2(float v, bf16* H, bf16* L, size_t o) {
    bf16 hb = __float2bfloat16(v);
    H[o] = hb;
    L[o] = __float2bfloat16(v - __bfloat162float(hb));
}
// swizzle for 64B-wide rows (GEMM tiles)
__device__ __forceinline__ uint32_t sw64(int row, int c16) {
    return (uint32_t)(row * 64 + ((c16 ^ ((row >> 1) & 3)) << 4));
}
// standard 128B swizzle for 128B-wide rows (flash tiles)
__device__ __forceinline__ uint32_t sw128(uint32_t off) {
    return off ^ ((off >> 3) & 0x70);
}

// ======================= fp16 2-product GEMM (projections) ======================
// C = (Ah+Al)[M,K] @ Bh[N,K]^T   (fp16 split A, hi-only fp16 B; residual ~2.8e-4)
// CTA tile 128x64, BK=32, 128 thr (4 warps 2x2, warp tile 64x32), 3-stage, occ 3.
// EPI=0: write fp32 C.  EPI=1: fused rope/split/transpose epilogue (one head/tile).
template <int EPI>
__global__ __launch_bounds__(128, 3)
void mma_gemm_kernel(const __half* __restrict__ Ah, const __half* __restrict__ Al,
                     const __half* __restrict__ Bh,
                     float* __restrict__ C, int K, int ldC,
                     const float* __restrict__ cs,
                     bf16* __restrict__ Qh, bf16* __restrict__ Ql,
                     bf16* __restrict__ Kh, bf16* __restrict__ Kl,
                     bf16* __restrict__ Vth, bf16* __restrict__ Vtl) {
    constexpr int ABYTES = 128 * 64;   // 8192
    constexpr int BBYTES = 64 * 64;    // 4096 (hi only)
    constexpr int STAGE  = 2 * ABYTES + BBYTES;   // 20480

    extern __shared__ char smem[];
    uint32_t sb = smem_to_u32(smem);

    int tid = threadIdx.x;
    int lane = tid & 31, wid = tid >> 5;
    int wm = wid & 1, wn = wid >> 1;      // 2x2 warp grid, warp tile 64x32

    int n0 = blockIdx.x * 64;
    int m0 = blockIdx.y * 128;

    float acc[4][4][4];
#pragma unroll
    for (int i = 0; i < 4; i++)
#pragma unroll
        for (int j = 0; j < 4; j++)
#pragma unroll
            for (int c = 0; c < 4; c++) acc[i][j][c] = 0.f;

    const int nkt = K >> 5;

    auto load_tiles = [&](int kt, int buf) {
        uint32_t base = sb + buf * STAGE;
#pragma unroll
        for (int it = 0; it < 4; it++) {
            int i = tid + it * 128;          // 512 A slots
            int r = i >> 2, c = i & 3;
            size_t g = (size_t)(m0 + r) * K + (size_t)kt * 32 + c * 8;
            uint32_t so = base + sw64(r, c);
            cp16(so, Ah + g);
            cp16(so + ABYTES, Al + g);
        }
#pragma unroll
        for (int it = 0; it < 2; it++) {
            int i = tid + it * 128;          // 256 B slots
            int r = i >> 2, c = i & 3;
            size_t g = (size_t)(n0 + r) * K + (size_t)kt * 32 + c * 8;
            cp16(base + 2 * ABYTES + sw64(r, c), Bh + g);
        }
    };

    load_tiles(0, 0);
    asm volatile("cp.async.commit_group;" ::: "memory");
    if (nkt > 1) {
        load_tiles(1, 1);
        asm volatile("cp.async.commit_group;" ::: "memory");
    }

    int stage = 0;
    for (int kt = 0; kt < nkt; kt++) {
        if (kt < nkt - 1) {
            asm volatile("cp.async.wait_group 1;" ::: "memory");
        } else {
            asm volatile("cp.async.wait_group 0;" ::: "memory");
        }
        __syncthreads();

        if (kt + 2 < nkt) {
            int nb = stage + 2; if (nb >= 3) nb -= 3;
            load_tiles(kt + 2, nb);
            asm volatile("cp.async.commit_group;" ::: "memory");
        }

        uint32_t abase = sb + stage * STAGE;
        uint32_t bbase = abase + 2 * ABYTES;

#pragma unroll
        for (int ks = 0; ks < 2; ks++) {
            int arow = wm * 64 + (lane & 15);
            int c16  = ks * 2 + (lane >> 4);

            uint32_t ah[4][4], al[4][4];
#pragma unroll
            for (int i = 0; i < 4; i++) {
                uint32_t ad = abase + sw64(arow + i * 16, c16);
                ldm_x4(ah[i], ad);
                ldm_x4(al[i], ad + ABYTES);
            }

            uint32_t bh[2][4];
            int brow = wn * 32 + (lane & 15);
#pragma unroll
            for (int g = 0; g < 2; g++)
                ldm_x4(bh[g], bbase + sw64(brow + g * 16, c16));

#pragma unroll
            for (int i = 0; i < 4; i++)
#pragma unroll
                for (int j = 0; j < 4; j++) {
                    int g = j >> 1, hf = j & 1;
                    uint32_t b0 = bh[g][hf], b1 = bh[g][hf + 2];
                    mma16816h(acc[i][j], ah[i], b0, b1);
                    mma16816h(acc[i][j], al[i], b0, b1);
                }
        }
        if (++stage == 3) stage = 0;
    }

    int r0 = lane >> 2, c0 = (lane & 3) * 2;

    if (EPI == 0) {
#pragma unroll
        for (int i = 0; i < 4; i++) {
            int row = m0 + wm * 64 + i * 16 + r0;
#pragma unroll
            for (int j = 0; j < 4; j++) {
                int col = n0 + wn * 32 + j * 8 + c0;
                *(float2*)&C[(size_t)row * ldC + col] =
                    make_float2(acc[i][j][0], acc[i][j][1]);
                *(float2*)&C[(size_t)(row + 8) * ldC + col] =
                    make_float2(acc[i][j][2], acc[i][j][3]);
            }
        }
        return;
    }

    // ===== fused qkv epilogue: one head per tile; stage through smem 128x65 f32 ==
    __syncthreads();
    float* st = (float*)smem;
#pragma unroll
    for (int i = 0; i < 4; i++) {
        int row = wm * 64 + i * 16 + r0;
#pragma unroll
        for (int j = 0; j < 4; j++) {
            int col = wn * 32 + j * 8 + c0;
            st[row * 65 + col]           = acc[i][j][0];
            st[row * 65 + col + 1]       = acc[i][j][1];
            st[(row + 8) * 65 + col]     = acc[i][j][2];
            st[(row + 8) * 65 + col + 1] = acc[i][j][3];
        }
    }
    __syncthreads();

    int mt = n0 >> 10;                // 0=q, 1=k, 2=v
    int h0 = (n0 & 1023) >> 6;        // the single head of this tile
    int nbase = m0 & 2047;
    int bb = m0 >> 11;

    if (mt < 2) {
        // RoPE + split into Q or K (bf16), [bh, n, 64]
        int i  = tid & 31;
        int rg = tid >> 5;            // 4 row groups of 32
        bf16* Hh = (mt == 0) ? Qh : Kh;
        bf16* Hl = (mt == 0) ? Ql : Kl;
        const float sc = (mt == 0) ? 0.125f * 1.44269504089f : 1.0f;
        size_t bhb = ((size_t)(bb * HH + h0)) * NN;
#pragma unroll 4
        for (int rr = 0; rr < 32; rr++) {
            int r = rg * 32 + rr;
            int n = nbase + r;
            float v1 = st[r * 65 + i];
            float v2 = st[r * 65 + i + 32];
            float2 csv = *(const float2*)&cs[(n * 32 + i) * 2];
            float a1 = sc * (v1 * csv.x - v2 * csv.y);
            float a2 = sc * (v2 * csv.x + v1 * csv.y);
            size_t ob = (bhb + n) * 64;
            split2(a1, Hh, Hl, ob + i);
            split2(a2, Hh, Hl, ob + i + 32);
        }
    } else {
        // V transpose + split into Vt (bf16) [bh, d, n]
        int dh = tid >> 6;            // d half (0..1)
        int np = (tid & 63) * 2;      // row pair
        size_t vb = ((size_t)(bb * HH + h0)) * 64;
#pragma unroll 4
        for (int dd = 0; dd < 32; dd++) {
            int d = dh * 32 + dd;
            float v0 = st[np * 65 + d];
            float v1 = st[(np + 1) * 65 + d];
            __nv_bfloat162 hv = __floats2bfloat162_rn(v0, v1);
            __nv_bfloat162 lv = __floats2bfloat162_rn(v0 - __bfloat162float(hv.x),
                                                      v1 - __bfloat162float(hv.y));
            size_t off = (vb + d) * NN + nbase + np;
            *(__nv_bfloat162*)&Vth[off] = hv;
            *(__nv_bfloat162*)&Vtl[off] = lv;
        }
    }
}

// ======================= fused flash attention (HMMA, bf16-split) ==============
// Per CTA: 64 q rows of one (b,h), 4 warps x 16 rows, 128 threads, 128B swizzle.
// Epilogue now writes fp16 aO splits (feeds fp16 out-projection).
__global__ __launch_bounds__(128, 3)
void flash_kernel(const bf16* __restrict__ Qh_, const bf16* __restrict__ Ql_,
                  const bf16* __restrict__ Kh_, const bf16* __restrict__ Kl_,
                  const bf16* __restrict__ Vh_, const bf16* __restrict__ Vl_,
                  __half* __restrict__ aOh, __half* __restrict__ aOl) {
    constexpr int FTILE = 8192;       // 64 rows x 128B, swizzled
    constexpr int FSTG  = 4 * FTILE;  // Kh,Kl,Vh,Vl

    extern __shared__ char smem[];
    uint32_t sb = smem_to_u32(smem);
    int tid = threadIdx.x, lane = tid & 31, wid = tid >> 5;
    int q0 = blockIdx.x * 64;
    int bh = blockIdx.y;
    int b = bh >> 4, h = bh & 15;

    const bf16* Qhp = Qh_ + ((size_t)bh * NN + q0) * 64;
    const bf16* Qlp = Ql_ + ((size_t)bh * NN + q0) * 64;
    const bf16* Khp = Kh_ + (size_t)bh * NN * 64;
    const bf16* Klp = Kl_ + (size_t)bh * NN * 64;
    const bf16* Vhp = Vh_ + (size_t)bh * 64 * NN;
    const bf16* Vlp = Vl_ + (size_t)bh * 64 * NN;

#pragma unroll
    for (int it = 0; it < 4; it++) {
        int i = tid + it * 128;
        int r = i >> 3, c = i & 7;
        uint32_t so = sw128((uint32_t)(r * 128 + c * 16));
        cp16(sb + so, Qhp + r * 64 + c * 8);
        cp16(sb + FTILE + so, Qlp + r * 64 + c * 8);
    }
    asm volatile("cp.async.commit_group;" ::: "memory");

    auto load_kv = [&](int kt, int buf) {
        uint32_t base = sb + buf * FSTG;
        int kv0 = kt * 64;
#pragma unroll
        for (int it = 0; it < 16; it++) {
            int i = tid + it * 128;
            int mat = i >> 9;
            int slot = i & 511;
            int r = slot >> 3, c = slot & 7;
            uint32_t so = base + mat * FTILE + sw128((uint32_t)(r * 128 + c * 16));
            const bf16* g;
            if (mat == 0)      g = Khp + (size_t)(kv0 + r) * 64 + c * 8;
            else if (mat == 1) g = Klp + (size_t)(kv0 + r) * 64 + c * 8;
            else if (mat == 2) g = Vhp + (size_t)r * NN + kv0 + c * 8;
            else               g = Vlp + (size_t)r * NN + kv0 + c * 8;
            cp16(so, g);
        }
    };

    load_kv(0, 1);
    asm volatile("cp.async.commit_group;" ::: "memory");
    asm volatile("cp.async.wait_group 1;" ::: "memory");
    __syncthreads();

    uint32_t qh[4][4], ql[4][4];
    {
        int arow = wid * 16 + (lane & 15);
#pragma unroll
        for (int ks = 0; ks < 4; ks++) {
            int c16 = ks * 2 + (lane >> 4);
            uint32_t so = sw128((uint32_t)(arow * 128 + c16 * 16));
            ldm_x4(qh[ks], sb + so);
            ldm_x4(ql[ks], sb + FTILE + so);
        }
    }
    __syncthreads();

    float o[8][4];
#pragma unroll
    for (int j = 0; j < 8; j++)
#pragma unroll
        for (int c = 0; c < 4; c++) o[j][c] = 0.f;
    float lpart[2] = {0.f, 0.f};

    for (int kt = 0; kt < NN / 64; kt++) {
        int cur = (kt + 1) & 1;
        if (kt + 1 < NN / 64) {
            load_kv(kt + 1, kt & 1);
            asm volatile("cp.async.commit_group;" ::: "memory");
            asm volatile("cp.async.wait_group 1;" ::: "memory");
        } else {
            asm volatile("cp.async.wait_group 0;" ::: "memory");
        }
        __syncthreads();

        uint32_t kb = sb + cur * FSTG;
        uint32_t vb = kb + 2 * FTILE;

        // ---- S = Q @ K^T (0.125*log2e pre-folded into Q) ----
        float s[8][4];
#pragma unroll
        for (int j = 0; j < 8; j++)
#pragma unroll
            for (int c = 0; c < 4; c++) s[j][c] = 0.f;
        {
            int brow = lane & 15;
#pragma unroll
            for (int ks = 0; ks < 4; ks++) {
                int c16 = ks * 2 + (lane >> 4);
                uint32_t khf[4][4], klf[4][4];
#pragma unroll
                for (int g = 0; g < 4; g++) {
                    uint32_t so = sw128((uint32_t)((g * 16 + brow) * 128 + c16 * 16));
                    ldm_x4(khf[g], kb + so);
                    ldm_x4(klf[g], kb + FTILE + so);
                }
#pragma unroll
                for (int g = 0; g < 4; g++)
#pragma unroll
                    for (int hf = 0; hf < 2; hf++) {
                        int j = g * 2 + hf;
                        mma16816(s[j], qh[ks], khf[g][hf], khf[g][hf + 2]);
                        mma16816(s[j], qh[ks], klf[g][hf], klf[g][hf + 2]);
                        mma16816(s[j], ql[ks], khf[g][hf], khf[g][hf + 2]);
                    }
            }
        }

        // ---- per-kc: V LDSM first (latency overlaps exp/pack), then PV ----
        {
            int vrow = lane & 15;
#pragma unroll
            for (int kc = 0; kc < 4; kc++) {
                uint32_t vhf[4][4], vlf[4][4];
#pragma unroll
                for (int g = 0; g < 4; g++) {
                    int c16 = kc * 2 + (lane >> 4);
                    uint32_t so = sw128((uint32_t)((g * 16 + vrow) * 128 + c16 * 16));
                    ldm_x4(vhf[g], vb + so);
                    ldm_x4(vlf[g], vb + FTILE + so);
                }

                uint32_t pa[4], pl[4];
#pragma unroll
                for (int t = 0; t < 2; t++) {
                    int j = kc * 2 + t;
#pragma unroll
                    for (int e = 0; e < 4; e++) s[j][e] = ex2(s[j][e]);
                    lpart[0] += s[j][0] + s[j][1];
                    lpart[1] += s[j][2] + s[j][3];
#pragma unroll
                    for (int e = 0; e < 2; e++) {
                        float x = s[j][e * 2], y = s[j][e * 2 + 1];
                        __nv_bfloat162 hv = __floats2bfloat162_rn(x, y);
                        float lx = x - __bfloat162float(hv.x);
                        float ly = y - __bfloat162float(hv.y);
                        __nv_bfloat162 lv = __floats2bfloat162_rn(lx, ly);
                        pa[t * 2 + e] = *(uint32_t*)&hv;
                        pl[t * 2 + e] = *(uint32_t*)&lv;
                    }
                }

#pragma unroll
                for (int g = 0; g < 4; g++)
#pragma unroll
                    for (int hf = 0; hf < 2; hf++) {
                        int dj = g * 2 + hf;
                        mma16816(o[dj], pa, vhf[g][hf], vhf[g][hf + 2]);
                        mma16816(o[dj], pl, vhf[g][hf], vhf[g][hf + 2]);
                        mma16816(o[dj], pa, vlf[g][hf], vlf[g][hf + 2]);
                    }
            }
        }
        __syncthreads();
    }

    // ---- epilogue: reduce row sums, normalize, split to fp16, write ----
    float lrow[2];
#pragma unroll
    for (int half = 0; half < 2; half++) {
        float rs = lpart[half];
        rs += __shfl_xor_sync(0xffffffffu, rs, 1);
        rs += __shfl_xor_sync(0xffffffffu, rs, 2);
        lrow[half] = rs;
    }
    float inv0 = 1.f / lrow[0], inv1 = 1.f / lrow[1];
    int r0 = q0 + wid * 16 + (lane >> 2);
    int cb = (lane & 3) * 2;
    size_t row0 = ((size_t)b * NN + r0) * 1024 + h * 64;
    size_t row1 = row0 + (size_t)8 * 1024;
#pragma unroll
    for (int dj = 0; dj < 8; dj++) {
        int col = dj * 8 + cb;
        float v0 = o[dj][0] * inv0, v1 = o[dj][1] * inv0;
        __half2 hv = __floats2half2_rn(v0, v1);
        __half2 lv = __floats2half2_rn(v0 - __half2float(__low2half(hv)),
                                       v1 - __half2float(__high2half(hv)));
        *(__half2*)&aOh[row0 + col] = hv;
        *(__half2*)&aOl[row0 + col] = lv;
        float v2 = o[dj][2] * inv1, v3 = o[dj][3] * inv1;
        hv = __floats2half2_rn(v2, v3);
        lv = __floats2half2_rn(v2 - __half2float(__low2half(hv)),
                               v3 - __half2float(__high2half(hv)));
        *(__half2*)&aOh[row1 + col] = hv;
        *(__half2*)&aOl[row1 + col] = lv;
    }
}

// ======================= small kernels (separate launches) =====================
__global__ void rope_table_kernel(float* __restrict__ cs) {
    int idx = blockIdx.x * blockDim.x + threadIdx.x;
    if (idx >= NN * 32) return;
    int n = idx >> 5, i = idx & 31;
    float inv = powf(10000.0f, -(float)i / 32.0f);
    float ang = (float)n * inv;
    float sv, cv;
    sincosf(ang, &sv, &cv);
    cs[idx * 2]     = cv;
    cs[idx * 2 + 1] = sv;
}

// x -> fp16 hi/lo split
__global__ void split_kernel(const float* __restrict__ src, __half* __restrict__ H,
                             __half* __restrict__ L, int n) {
    int i = (blockIdx.x * blockDim.x + threadIdx.x) * 4;
    if (i >= n) return;
    float4 v = *(const float4*)(src + i);
    __half2 h0 = __floats2half2_rn(v.x, v.y);
    __half2 h1 = __floats2half2_rn(v.z, v.w);
    __half2 l0 = __floats2half2_rn(v.x - __half2float(__low2half(h0)),
                                   v.y - __half2float(__high2half(h0)));
    __half2 l1 = __floats2half2_rn(v.z - __half2float(__low2half(h1)),
                                   v.w - __half2float(__high2half(h1)));
    *(__half2*)&H[i]     = h0;
    *(__half2*)&H[i + 2] = h1;
    *(__half2*)&L[i]     = l0;
    *(__half2*)&L[i + 2] = l1;
}

// W:[K,N] row-major -> T:[N,K] fp16 hi-only
__global__ __launch_bounds__(256)
void wtrans_kernel(const float* __restrict__ W, __half* __restrict__ Th,
                   int K, int N) {
    __shared__ float t[32][33];
    int n0 = blockIdx.x * 32, k0 = blockIdx.y * 32;
    int tx = threadIdx.x, ty = threadIdx.y;
#pragma unroll
    for (int s = 0; s < 32; s += 8)
        t[ty + s][tx] = W[(size_t)(k0 + ty + s) * N + n0 + tx];
    __syncthreads();
#pragma unroll
    for (int s = 0; s < 32; s += 8)
        Th[(size_t)(n0 + ty + s) * K + k0 + tx] = __float2half_rn(t[tx][ty + s]);
}

// ======================= launch =======================
extern "C" void kernel_launch(void* const* d_in, const int* in_sizes, int n_in,
                              void* d_out, int out_size) {
    const float* x     = (const float*)d_in[0];
    const float* w_qkv = (const float*)d_in[1];
    const float* w_out = (const float*)d_in[2];
    float* out = (float*)d_out;

    float *cs;
    __half *xh, *xl, *wqTh, *woTh, *aOh, *aOl;
    bf16 *Qh, *Ql, *Kh, *Kl, *Vth, *Vtl;
    cudaGetSymbolAddress((void**)&cs,  g_cs);
    cudaGetSymbolAddress((void**)&xh,  g_xh);   cudaGetSymbolAddress((void**)&xl,  g_xl);
    cudaGetSymbolAddress((void**)&wqTh, g_wqTh);
    cudaGetSymbolAddress((void**)&woTh, g_woTh);
    cudaGetSymbolAddress((void**)&Qh, g_Qh);    cudaGetSymbolAddress((void**)&Ql, g_Ql);
    cudaGetSymbolAddress((void**)&Kh, g_Kh);    cudaGetSymbolAddress((void**)&Kl, g_Kl);
    cudaGetSymbolAddress((void**)&Vth, g_Vth);  cudaGetSymbolAddress((void**)&Vtl, g_Vtl);
    cudaGetSymbolAddress((void**)&aOh, g_aOh);  cudaGetSymbolAddress((void**)&aOl, g_aOl);

    const int SMEM_GEMM = 3 * 20480;       // 61440 (>= 128*65*4 = 33280 for epilogue)
    const int FLASH_SMEM = 2 * 4 * 8192;   // 65536
    cudaFuncSetAttribute(mma_gemm_kernel<0>,
                         cudaFuncAttributeMaxDynamicSharedMemorySize, SMEM_GEMM);
    cudaFuncSetAttribute(mma_gemm_kernel<1>,
                         cudaFuncAttributeMaxDynamicSharedMemorySize, SMEM_GEMM);
    cudaFuncSetAttribute(flash_kernel,
                         cudaFuncAttributeMaxDynamicSharedMemorySize, FLASH_SMEM);

    // 0) rope table + split input / transpose weights (separate launches)
    rope_table_kernel<<<(NN * 32 + 255) / 256, 256>>>(cs);
    split_kernel<<<(MTOT * 1024 / 4 + 255) / 256, 256>>>(x, xh, xl, MTOT * 1024);
    wtrans_kernel<<<dim3(3072 / 32, 1024 / 32), dim3(32, 8)>>>(w_qkv, wqTh, 1024, 3072);
    wtrans_kernel<<<dim3(1024 / 32, 1024 / 32), dim3(32, 8)>>>(w_out, woTh, 1024, 1024);

    // 1) qkv GEMM (fp16 2-product) with fused rope/split/transpose epilogue
    mma_gemm_kernel<1><<<dim3(3072 / 64, 4096 / 128), 128, SMEM_GEMM>>>(
        xh, xl, wqTh, nullptr, 1024, 0,
        cs, Qh, Ql, Kh, Kl, Vth, Vtl);

    // 2) fused flash attention (bf16 3-product) -> fp16 aO splits [B*N, 1024]
    flash_kernel<<<dim3(NN / 64, BHT), 128, FLASH_SMEM>>>(
        Qh, Ql, Kh, Kl, Vth, Vtl, aOh, aOl);

    // 3) out = aO @ w_out  (fp16 2-product, M=4096, N=1024, K=1024)
    mma_gemm_kernel<0><<<dim3(1024 / 64, 4096 / 128), 128, SMEM_GEMM>>>(
        aOh, aOl, woTh, out, 1024, 1024,
        nullptr, nullptr, nullptr, nullptr, nullptr, nullptr, nullptr);
}